// round 2
// baseline (speedup 1.0000x reference)
#include <cuda_runtime.h>

// ---------------- problem constants ----------------
#define BB    4
#define NPTS  8192
#define MC    1024
#define NSAMP 16
#define CFEAT 64
#define RAD2  0.25f
#define EPSBN 1e-5f

// ---------------- scratch (__device__ globals; no runtime alloc) ----------------
static __device__ float g_featin[(size_t)BB*67*NPTS];
static __device__ float g_y1[(size_t)BB*64*NPTS];
static __device__ float g_y2[(size_t)BB*128*NPTS];
static __device__ float g_y3[(size_t)BB*256*NPTS];
static __device__ float g_nft[(size_t)BB*NPTS*256];     // new_features transposed [b,n,256]
static __device__ int   g_idx1[BB*MC*NSAMP];
static __device__ int   g_idx2[BB*MC*NSAMP];
static __device__ float g_ip[(size_t)BB*259*MC*NSAMP];  // [b,ch,slot,center]
static __device__ float g_q[(size_t)BB*8*MC*NSAMP];
static __device__ float g_k[(size_t)BB*8*MC*NSAMP];
static __device__ float g_v[(size_t)BB*256*MC*NSAMP];
static __device__ float g_P[(size_t)BB*NSAMP*MC*MC];    // softmaxed att [b,slot,j,n] (256MB)
static __device__ float g_off[(size_t)BB*256*MC*NSAMP];
static __device__ float g_yf[(size_t)BB*256*MC*NSAMP];
static __device__ float g_pool[(size_t)BB*256*MC];
static __device__ float g_yo[(size_t)BB*512*MC];
static __device__ float g_st1[2*64], g_st2[2*128], g_st3[2*256], g_stf[2*256], g_sto[2*512];
static __device__ float g_sb1[2*64], g_sb2[2*128], g_sb3[2*256], g_sbf[2*256], g_sbo[2*512];

// ---------------- build concat(xyz^T, features) ----------------
__global__ void k_featin(const float* __restrict__ xyz, const float* __restrict__ feats,
                         float* __restrict__ out)
{
    int i = blockIdx.x * 256 + threadIdx.x;
    if (i >= BB*67*NPTS) return;
    int n  = i % NPTS;
    int ch = (i / NPTS) % 67;
    int b  = i / (NPTS*67);
    float v;
    if (ch < 3) v = xyz[((size_t)b*NPTS + n)*3 + ch];
    else        v = feats[((size_t)b*CFEAT + (ch-3))*NPTS + n];
    out[i] = v;
}

// ---------------- generic GEMM: Y[b,o,col] = sum_c W[o,c]*f(X[b,c,col]) ----------------
// MODE 0: plain. MODE 1: relu(x*sb[c]+sb[Cin+c]).  STATS: accumulate per-row sum/sumsq.
template<int MODE, int STATS>
__global__ void k_gemm(const float* __restrict__ W, const float* __restrict__ X,
                       float* __restrict__ Y, int Cin, int Cout, int NCOL,
                       const float* __restrict__ sb, float* __restrict__ stats)
{
    const int b = blockIdx.z;
    const float* Xb = X + (size_t)b * Cin * NCOL;
    float* Yb = Y + (size_t)b * Cout * NCOL;
    const int col0 = blockIdx.x * 64;
    const int row0 = blockIdx.y * 64;
    __shared__ float Ws[16][68];
    __shared__ float Xs[16][68];
    const int tid = threadIdx.x;
    const int tx = tid & 15, ty = tid >> 4;
    float acc[4][4];
#pragma unroll
    for (int i = 0; i < 4; i++)
#pragma unroll
        for (int j = 0; j < 4; j++) acc[i][j] = 0.f;

    for (int k0 = 0; k0 < Cin; k0 += 16) {
        {
            int kk = tid & 15, r = tid >> 4;
#pragma unroll
            for (int i = 0; i < 4; i++) {
                int rr = r + i*16;
                float w = 0.f;
                if (row0+rr < Cout && k0+kk < Cin) w = W[(size_t)(row0+rr)*Cin + k0+kk];
                Ws[kk][rr] = w;
            }
            int col = tid & 63, c4 = tid >> 6;
#pragma unroll
            for (int i = 0; i < 4; i++) {
                int cc = c4 + i*4;
                float v = 0.f;
                int cg = k0 + cc, colg = col0 + col;
                if (cg < Cin && colg < NCOL) {
                    v = Xb[(size_t)cg*NCOL + colg];
                    if (MODE == 1) v = fmaxf(fmaf(v, sb[cg], sb[Cin+cg]), 0.f);
                }
                Xs[cc][col] = v;
            }
        }
        __syncthreads();
#pragma unroll
        for (int kk = 0; kk < 16; kk++) {
            float4 wv4 = *(const float4*)&Ws[kk][ty*4];
            float4 xv4 = *(const float4*)&Xs[kk][tx*4];
            float wv[4] = {wv4.x, wv4.y, wv4.z, wv4.w};
            float xv[4] = {xv4.x, xv4.y, xv4.z, xv4.w};
#pragma unroll
            for (int i = 0; i < 4; i++)
#pragma unroll
                for (int j = 0; j < 4; j++) acc[i][j] = fmaf(wv[i], xv[j], acc[i][j]);
        }
        __syncthreads();
    }

    float rs[4], rq[4];
#pragma unroll
    for (int i = 0; i < 4; i++) { rs[i] = 0.f; rq[i] = 0.f; }
#pragma unroll
    for (int i = 0; i < 4; i++) {
        int r = row0 + ty*4 + i;
        if (r < Cout) {
#pragma unroll
            for (int j = 0; j < 4; j++) {
                int cidx = col0 + tx*4 + j;
                if (cidx < NCOL) {
                    float v = acc[i][j];
                    Yb[(size_t)r*NCOL + cidx] = v;
                    rs[i] += v; rq[i] += v*v;
                }
            }
        }
    }
    if (STATS) {
#pragma unroll
        for (int i = 0; i < 4; i++) {
            float s = rs[i], q2 = rq[i];
#pragma unroll
            for (int o = 8; o > 0; o >>= 1) {
                s  += __shfl_down_sync(0xffffffffu, s, o);
                q2 += __shfl_down_sync(0xffffffffu, q2, o);
            }
            if (tx == 0) {
                int r = row0 + ty*4 + i;
                if (r < Cout) { atomicAdd(&stats[r], s); atomicAdd(&stats[Cout + r], q2); }
            }
        }
    }
}

// ---------------- BN finalize: stats -> (scale, bias) ----------------
__global__ void k_fin(const float* __restrict__ stats, const float* __restrict__ g,
                      const float* __restrict__ be, float* __restrict__ sb,
                      int Cc, float invcnt)
{
    int c = blockIdx.x * 64 + threadIdx.x;
    if (c >= Cc) return;
    float mu  = stats[c] * invcnt;
    float var = stats[Cc + c] * invcnt - mu*mu;
    float s = g[c] * rsqrtf(var + EPSBN);
    sb[c] = s;
    sb[Cc + c] = be[c] - mu * s;
}

// ---------------- ball query: first NSAMP indices (in order) within radius ----------------
__global__ void k_bq(const float* __restrict__ src, const float* __restrict__ ctr,
                     int* __restrict__ out, int NSRC)
{
    int gw = (blockIdx.x * blockDim.x + threadIdx.x) >> 5;
    int lane = threadIdx.x & 31;
    __shared__ int lists[8][NSAMP];
    int* list = lists[threadIdx.x >> 5];
    if (gw >= BB*MC) return;
    int b = gw / MC, m = gw % MC;
    float cx = ctr[((size_t)b*MC + m)*3 + 0];
    float cy = ctr[((size_t)b*MC + m)*3 + 1];
    float cz = ctr[((size_t)b*MC + m)*3 + 2];
    int count = 0;
    for (int base = 0; base < NSRC; base += 32) {
        int n = base + lane;
        bool ok = false;
        if (n < NSRC) {
            float dx = src[((size_t)b*NSRC + n)*3 + 0] - cx;
            float dy = src[((size_t)b*NSRC + n)*3 + 1] - cy;
            float dz = src[((size_t)b*NSRC + n)*3 + 2] - cz;
            ok = (dx*dx + dy*dy + dz*dz) < RAD2;
        }
        unsigned mk = __ballot_sync(0xffffffffu, ok);
        if (ok) {
            int pos = count + __popc(mk & ((1u << lane) - 1u));
            if (pos < NSAMP) list[pos] = n;
        }
        count += __popc(mk);
        if (count >= NSAMP) break;
    }
    __syncwarp();
    if (lane < NSAMP) {
        int v;
        if (count == 0) v = 0;
        else v = (lane < count) ? list[lane] : list[0];
        out[((size_t)b*MC + m)*NSAMP + lane] = v;
    }
}

// ---------------- new_features transpose with affine+relu: [b,c,n] -> [b,n,c] ----------------
__global__ void k_nft(const float* __restrict__ y3, const float* __restrict__ sb3,
                      float* __restrict__ nft)
{
    int b = blockIdx.z;
    int n0 = blockIdx.x * 32, c0 = blockIdx.y * 32;
    __shared__ float t[32][33];
#pragma unroll
    for (int i = 0; i < 4; i++) {
        int c = c0 + threadIdx.y + i*8;
        int n = n0 + threadIdx.x;
        float v = y3[((size_t)b*256 + c)*NPTS + n];
        v = fmaxf(fmaf(v, sb3[c], sb3[256 + c]), 0.f);
        t[threadIdx.y + i*8][threadIdx.x] = v;
    }
    __syncthreads();
#pragma unroll
    for (int i = 0; i < 4; i++) {
        int n = n0 + threadIdx.y + i*8;
        int c = c0 + threadIdx.x;
        nft[((size_t)b*NPTS + n)*256 + c] = t[threadIdx.x][threadIdx.y + i*8];
    }
}

// ---------------- build ip [b,259,slot,center]: gathered features + rel xyz ----------------
__global__ void k_ip(const float* __restrict__ nft, const int* __restrict__ idx1,
                     const int* __restrict__ idx2, const float* __restrict__ xyz,
                     const float* __restrict__ ctr, float* __restrict__ ip)
{
    int bz = blockIdx.x;
    int cblk = bz & 31;
    int slot = (bz >> 5) & 15;
    int b    = bz >> 9;
    __shared__ float s[256][33];
    int warp = threadIdx.x >> 5, lane = threadIdx.x & 31;
#pragma unroll
    for (int w = 0; w < 4; w++) {
        int center = cblk*32 + warp*4 + w;
        int id = idx1[((size_t)b*MC + center)*NSAMP + slot];
        const float* srcp = nft + ((size_t)b*NPTS + id)*256;
#pragma unroll
        for (int t = 0; t < 8; t++) s[lane + t*32][warp*4 + w] = srcp[lane + t*32];
    }
    __syncthreads();
    int center = threadIdx.x & 31, chb = threadIdx.x >> 5;
#pragma unroll
    for (int t = 0; t < 32; t++) {
        int ch = chb + t*8;
        ip[(((size_t)b*259 + ch)*NSAMP + slot)*MC + cblk*32 + center] = s[ch][center];
    }
    if (threadIdx.x < 96) {
        int d = threadIdx.x / 32;
        int cc = threadIdx.x & 31;
        int ctr_i = cblk*32 + cc;
        int i1 = idx1[((size_t)b*MC + ctr_i)*NSAMP + slot];
        int i2 = idx2[((size_t)b*MC + ctr_i)*NSAMP + slot];
        float r = ctr[((size_t)b*MC + i2)*3 + d] - xyz[((size_t)b*NPTS + i1)*3 + d];
        ip[(((size_t)b*259 + 256 + d)*NSAMP + slot)*MC + ctr_i] = r;
    }
}

// ---------------- attention logits + column softmax over n (one CTA per column j) --------
__global__ void k_att(const float* __restrict__ q, const float* __restrict__ k,
                      float* __restrict__ P)
{
    int bx = blockIdx.x;
    int j = bx & (MC-1);
    int slot = (bx >> 10) & 15;
    int b = bx >> 14;
    __shared__ float red[256];
    float qv[8];
#pragma unroll
    for (int c = 0; c < 8; c++)
        qv[c] = q[(((size_t)b*8 + c)*NSAMP + slot)*MC + j];
    const float* kb = k + ((size_t)b*8*NSAMP + slot)*MC;
    float s[4];
#pragma unroll
    for (int t = 0; t < 4; t++) {
        int n = threadIdx.x + t*256;
        float a = 0.f;
#pragma unroll
        for (int c = 0; c < 8; c++) a = fmaf(kb[(size_t)c*NSAMP*MC + n], qv[c], a);
        s[t] = a;
    }
    float mx = fmaxf(fmaxf(s[0], s[1]), fmaxf(s[2], s[3]));
    red[threadIdx.x] = mx; __syncthreads();
    for (int o = 128; o > 0; o >>= 1) {
        if (threadIdx.x < o) red[threadIdx.x] = fmaxf(red[threadIdx.x], red[threadIdx.x + o]);
        __syncthreads();
    }
    mx = red[0]; __syncthreads();
    float es[4]; float sum = 0.f;
#pragma unroll
    for (int t = 0; t < 4; t++) { es[t] = __expf(s[t] - mx); sum += es[t]; }
    red[threadIdx.x] = sum; __syncthreads();
    for (int o = 128; o > 0; o >>= 1) {
        if (threadIdx.x < o) red[threadIdx.x] += red[threadIdx.x + o];
        __syncthreads();
    }
    float inv = 1.f / red[0];
    float* Pb = P + (((size_t)(b*NSAMP + slot))*MC + j)*MC;
#pragma unroll
    for (int t = 0; t < 4; t++) Pb[threadIdx.x + t*256] = es[t] * inv;
}

// ---------------- att_feat = V * P^T, fused "- group_features" -> off ----------------
__global__ void k_attfeat(const float* __restrict__ V, const float* __restrict__ P,
                          const float* __restrict__ ip, float* __restrict__ off)
{
    int bs = blockIdx.z;
    int slot = bs & 15, b = bs >> 4;
    const float* Vb = V + ((size_t)b*256*NSAMP + slot)*MC;           // row c: +c*16384
    const float* Pb = P + ((size_t)(b*NSAMP + slot))*MC*MC;          // row j: +j*1024
    int j0 = blockIdx.x * 64, c0 = blockIdx.y * 64;
    __shared__ float Vs[16][68], Ps[16][68];
    const int tid = threadIdx.x, tx = tid & 15, ty = tid >> 4;
    float acc[4][4];
#pragma unroll
    for (int i = 0; i < 4; i++)
#pragma unroll
        for (int j = 0; j < 4; j++) acc[i][j] = 0.f;

    for (int n0 = 0; n0 < MC; n0 += 16) {
        int nn = tid & 15, r = tid >> 4;
#pragma unroll
        for (int i = 0; i < 4; i++) {
            int rr = r + i*16;
            Vs[nn][rr] = Vb[(size_t)(c0+rr)*NSAMP*MC + n0 + nn];
            Ps[nn][rr] = Pb[(size_t)(j0+rr)*MC + n0 + nn];
        }
        __syncthreads();
#pragma unroll
        for (int kk = 0; kk < 16; kk++) {
            float4 a4 = *(const float4*)&Vs[kk][ty*4];
            float4 p4 = *(const float4*)&Ps[kk][tx*4];
            float av[4] = {a4.x, a4.y, a4.z, a4.w};
            float pv[4] = {p4.x, p4.y, p4.z, p4.w};
#pragma unroll
            for (int i = 0; i < 4; i++)
#pragma unroll
                for (int j = 0; j < 4; j++) acc[i][j] = fmaf(av[i], pv[j], acc[i][j]);
        }
        __syncthreads();
    }
#pragma unroll
    for (int i = 0; i < 4; i++) {
        int c = c0 + ty*4 + i;
#pragma unroll
        for (int j = 0; j < 4; j++) {
            int jj = j0 + tx*4 + j;
            float gf = ip[(((size_t)b*259 + c)*NSAMP + slot)*MC + jj];
            off[(((size_t)b*256 + c)*NSAMP + slot)*MC + jj] = acc[i][j] - gf;
        }
    }
}

// ---------------- relu(affine(yf)) + gf residual, max-pool over slot ----------------
__global__ void k_pool(const float* __restrict__ yf, const float* __restrict__ sbf,
                       const float* __restrict__ ip, float* __restrict__ pool)
{
    int i = blockIdx.x * 256 + threadIdx.x;
    if (i >= BB*256*MC) return;
    int center = i & (MC-1);
    int c = (i >> 10) & 255;
    int b = i >> 18;
    float s = sbf[c], bi = sbf[256 + c];
    float mx = -1e30f;
#pragma unroll
    for (int slot = 0; slot < NSAMP; slot++) {
        float v = fmaxf(fmaf(yf[(((size_t)b*256 + c)*NSAMP + slot)*MC + center], s, bi), 0.f);
        v += ip[(((size_t)b*259 + c)*NSAMP + slot)*MC + center];
        mx = fmaxf(mx, v);
    }
    pool[((size_t)b*256 + c)*MC + center] = mx;
}

// ---------------- final: out = [ctr_xyz (optional), relu(affine(yo))] ----------------
__global__ void k_final(const float* __restrict__ yo, const float* __restrict__ sbo,
                        const float* __restrict__ ctr, float* __restrict__ out, int has_ctr)
{
    int off0 = has_ctr ? BB*MC*3 : 0;
    int total = off0 + BB*512*MC;
    int i = blockIdx.x * 256 + threadIdx.x;
    if (i >= total) return;
    if (i < off0) { out[i] = ctr[i]; return; }
    int j = i - off0;
    int ch = (j >> 10) & 511;
    out[i] = fmaxf(fmaf(yo[j], sbo[ch], sbo[512 + ch]), 0.f);
}

// ---------------- host launch ----------------
extern "C" void kernel_launch(void* const* d_in, const int* in_sizes, int n_in,
                              void* d_out, int out_size)
{
    const float* xyz   = (const float*)d_in[0];
    const float* feats = (const float*)d_in[1];
    const float* ctr   = (const float*)d_in[2];
    const float* W1 = (const float*)d_in[3];
    const float* g1 = (const float*)d_in[4];
    const float* b1 = (const float*)d_in[5];
    const float* W2 = (const float*)d_in[6];
    const float* g2 = (const float*)d_in[7];
    const float* b2 = (const float*)d_in[8];
    const float* W3 = (const float*)d_in[9];
    const float* g3 = (const float*)d_in[10];
    const float* b3 = (const float*)d_in[11];
    const float* Wq = (const float*)d_in[12];
    const float* Wk = (const float*)d_in[13];
    const float* Wv = (const float*)d_in[14];
    const float* Wf = (const float*)d_in[15];
    const float* gp = (const float*)d_in[16];
    const float* bp = (const float*)d_in[17];
    const float* Wo = (const float*)d_in[18];
    const float* go = (const float*)d_in[19];
    const float* bo = (const float*)d_in[20];
    float* outp = (float*)d_out;

    float *featin, *y1, *y2, *y3, *nft, *ip, *qb, *kb, *vb, *Pb, *offb, *yf, *pool, *yo;
    int *idx1, *idx2;
    float *st1, *st2, *st3, *stf, *sto, *sb1, *sb2, *sb3, *sbf, *sbo;
    cudaGetSymbolAddress((void**)&featin, g_featin);
    cudaGetSymbolAddress((void**)&y1, g_y1);
    cudaGetSymbolAddress((void**)&y2, g_y2);
    cudaGetSymbolAddress((void**)&y3, g_y3);
    cudaGetSymbolAddress((void**)&nft, g_nft);
    cudaGetSymbolAddress((void**)&idx1, g_idx1);
    cudaGetSymbolAddress((void**)&idx2, g_idx2);
    cudaGetSymbolAddress((void**)&ip, g_ip);
    cudaGetSymbolAddress((void**)&qb, g_q);
    cudaGetSymbolAddress((void**)&kb, g_k);
    cudaGetSymbolAddress((void**)&vb, g_v);
    cudaGetSymbolAddress((void**)&Pb, g_P);
    cudaGetSymbolAddress((void**)&offb, g_off);
    cudaGetSymbolAddress((void**)&yf, g_yf);
    cudaGetSymbolAddress((void**)&pool, g_pool);
    cudaGetSymbolAddress((void**)&yo, g_yo);
    cudaGetSymbolAddress((void**)&st1, g_st1);
    cudaGetSymbolAddress((void**)&st2, g_st2);
    cudaGetSymbolAddress((void**)&st3, g_st3);
    cudaGetSymbolAddress((void**)&stf, g_stf);
    cudaGetSymbolAddress((void**)&sto, g_sto);
    cudaGetSymbolAddress((void**)&sb1, g_sb1);
    cudaGetSymbolAddress((void**)&sb2, g_sb2);
    cudaGetSymbolAddress((void**)&sb3, g_sb3);
    cudaGetSymbolAddress((void**)&sbf, g_sbf);
    cudaGetSymbolAddress((void**)&sbo, g_sbo);

    cudaMemsetAsync(st1, 0, sizeof(float)*2*64,  0);
    cudaMemsetAsync(st2, 0, sizeof(float)*2*128, 0);
    cudaMemsetAsync(st3, 0, sizeof(float)*2*256, 0);
    cudaMemsetAsync(stf, 0, sizeof(float)*2*256, 0);
    cudaMemsetAsync(sto, 0, sizeof(float)*2*512, 0);

    // stage 0: concat input
    k_featin<<<(BB*67*NPTS + 255)/256, 256>>>(xyz, feats, featin);

    // MLP stages with batch-stats BN folded into next stage
    k_gemm<0,1><<<dim3(NPTS/64, 1, BB), 256>>>(W1, featin, y1, 67, 64, NPTS, nullptr, st1);
    k_fin<<<1, 64>>>(st1, g1, b1, sb1, 64, 1.f/(BB*NPTS));
    k_gemm<1,1><<<dim3(NPTS/64, 2, BB), 256>>>(W2, y1, y2, 64, 128, NPTS, sb1, st2);
    k_fin<<<2, 64>>>(st2, g2, b2, sb2, 128, 1.f/(BB*NPTS));
    k_gemm<1,1><<<dim3(NPTS/64, 4, BB), 256>>>(W3, y2, y3, 128, 256, NPTS, sb2, st3);
    k_fin<<<4, 64>>>(st3, g3, b3, sb3, 256, 1.f/(BB*NPTS));

    // new_features transposed to n-major (coalesced gathers)
    k_nft<<<dim3(NPTS/32, 8, BB), dim3(32, 8)>>>(y3, sb3, nft);

    // ball queries
    k_bq<<<(BB*MC*32 + 255)/256, 256>>>(xyz, ctr, idx1, NPTS);
    k_bq<<<(BB*MC*32 + 255)/256, 256>>>(ctr, ctr, idx2, MC);

    // gather ip = [group_features ; rel]
    k_ip<<<BB*16*32, 256>>>(nft, idx1, idx2, xyz, ctr, ip);

    // q, k, v projections
    k_gemm<0,0><<<dim3(256, 1, BB), 256>>>(Wq, ip, qb, 259, 8,   MC*NSAMP, nullptr, nullptr);
    k_gemm<0,0><<<dim3(256, 1, BB), 256>>>(Wk, ip, kb, 259, 8,   MC*NSAMP, nullptr, nullptr);
    k_gemm<0,0><<<dim3(256, 4, BB), 256>>>(Wv, ip, vb, 259, 256, MC*NSAMP, nullptr, nullptr);

    // attention: logits + softmax over n, then att_feat = V P^T fused with -gf
    k_att<<<BB*NSAMP*MC, 256>>>(qb, kb, Pb);
    k_attfeat<<<dim3(16, 4, BB*NSAMP), 256>>>(vb, Pb, ip, offb);

    // Wf + BN stats, pool (affine+relu+residual+max over slot)
    k_gemm<0,1><<<dim3(256, 4, BB), 256>>>(Wf, offb, yf, 256, 256, MC*NSAMP, nullptr, stf);
    k_fin<<<4, 64>>>(stf, gp, bp, sbf, 256, 1.f/(BB*MC*NSAMP));
    k_pool<<<(BB*256*MC + 255)/256, 256>>>(yf, sbf, ip, pool);

    // output conv + BN
    k_gemm<0,1><<<dim3(MC/64, 8, BB), 256>>>(Wo, pool, yo, 256, 512, MC, nullptr, sto);
    k_fin<<<8, 64>>>(sto, go, bo, sbo, 512, 1.f/(BB*MC));

    int has_ctr = (out_size == BB*MC*3 + BB*512*MC) ? 1 : 0;
    int total = (has_ctr ? BB*MC*3 : 0) + BB*512*MC;
    k_final<<<(total + 255)/256, 256>>>(yo, sbo, ctr, outp, has_ctr);
}

// round 3
// speedup vs baseline: 1.0020x; 1.0020x over previous
#include <cuda_runtime.h>

// ---------------- problem constants ----------------
#define BB    4
#define NPTS  8192
#define MC    1024
#define NSAMP 16
#define CFEAT 64
#define RAD2  0.25f
#define EPSBN 1e-5f

#define FMA2(acc, a, b) asm("fma.rn.f32x2 %0, %1, %2, %0;" : "+l"(acc) : "l"(a), "l"(b))

// ---------------- scratch (__device__ globals; no runtime alloc) ----------------
static __device__ float g_featin[(size_t)BB*67*NPTS];
static __device__ float g_y1[(size_t)BB*64*NPTS];
static __device__ float g_y2[(size_t)BB*128*NPTS];
static __device__ float g_y3[(size_t)BB*256*NPTS];
static __device__ float g_nft[(size_t)BB*NPTS*256];     // new_features transposed [b,n,256]
static __device__ int   g_idx1[BB*MC*NSAMP];
static __device__ int   g_idx2[BB*MC*NSAMP];
static __device__ float g_ip[(size_t)BB*259*MC*NSAMP];  // [b,ch,slot,center]
static __device__ float g_q[(size_t)BB*8*MC*NSAMP];
static __device__ float g_k[(size_t)BB*8*MC*NSAMP];
static __device__ float g_v[(size_t)BB*256*MC*NSAMP];
static __device__ float g_P[(size_t)BB*NSAMP*MC*MC];    // softmaxed att [b,slot,j,n] (256MB)
static __device__ float g_off[(size_t)BB*256*MC*NSAMP];
static __device__ float g_yf[(size_t)BB*256*MC*NSAMP];
static __device__ float g_pool[(size_t)BB*256*MC];
static __device__ float g_yo[(size_t)BB*512*MC];
static __device__ float g_st1[2*64], g_st2[2*128], g_st3[2*256], g_stf[2*256], g_sto[2*512];
static __device__ float g_sb1[2*64], g_sb2[2*128], g_sb3[2*256], g_sbf[2*256], g_sbo[2*512];

// ---------------- build concat(xyz^T, features) ----------------
__global__ void k_featin(const float* __restrict__ xyz, const float* __restrict__ feats,
                         float* __restrict__ out)
{
    int i = blockIdx.x * 256 + threadIdx.x;
    if (i >= BB*67*NPTS) return;
    int n  = i % NPTS;
    int ch = (i / NPTS) % 67;
    int b  = i / (NPTS*67);
    float v;
    if (ch < 3) v = xyz[((size_t)b*NPTS + n)*3 + ch];
    else        v = feats[((size_t)b*CFEAT + (ch-3))*NPTS + n];
    out[i] = v;
}

// ======== packed-f32x2 GEMM: Y[b,o,col] = sum_c W[o,c]*f(X[b,c,col]) ========
// Tile 64 rows x 128 cols, 256 threads, per-thread 4 rows x 8 cols, K-chunk 16.
// Requires Cout % 64 == 0, NCOL % 128 == 0.
// MODE 0: plain X. MODE 1: relu(x*sb[c]+sb[Cin+c]).  STATS: per-row sum/sumsq atomics.
template<int MODE, int STATS>
__global__ void k_gemm2(const float* __restrict__ W, const float* __restrict__ X,
                        float* __restrict__ Y, int Cin, int Cout, int NCOL,
                        const float* __restrict__ sb, float* __restrict__ stats)
{
    const int b = blockIdx.z;
    const float* Xb = X + (size_t)b * Cin * NCOL;
    float* Yb = Y + (size_t)b * Cout * NCOL;
    const int col0 = blockIdx.x * 128;
    const int row0 = blockIdx.y * 64;
    __shared__ float Wd[16][132];   // duplicated: Wd[kk][2r]=Wd[kk][2r+1]=W[row0+r][k0+kk]
    __shared__ float Xs[16][132];
    const int tid = threadIdx.x;
    const int tx = tid & 15, ty = tid >> 4;

    unsigned long long acc[4][4];
#pragma unroll
    for (int i = 0; i < 4; i++)
#pragma unroll
        for (int p = 0; p < 4; p++) acc[i][p] = 0ull;

    for (int k0 = 0; k0 < Cin; k0 += 16) {
        // load W duplicated
        {
            int kk = tid & 15, rbase = tid >> 4;
#pragma unroll
            for (int pass = 0; pass < 4; pass++) {
                int rr = rbase + pass*16;
                float w = 0.f;
                if (k0 + kk < Cin) w = W[(size_t)(row0+rr)*Cin + k0 + kk];
                *(float2*)&Wd[kk][2*rr] = make_float2(w, w);
            }
        }
        // load X tile
        {
            int col = tid & 127, kb = tid >> 7;
#pragma unroll
            for (int t = 0; t < 8; t++) {
                int kk = kb + 2*t;
                float v = 0.f;
                int cg = k0 + kk;
                if (cg < Cin) {
                    v = Xb[(size_t)cg*NCOL + col0 + col];
                    if (MODE == 1) v = fmaxf(fmaf(v, sb[cg], sb[Cin+cg]), 0.f);
                }
                Xs[kk][col] = v;
            }
        }
        __syncthreads();
#pragma unroll
        for (int kk = 0; kk < 16; kk++) {
            ulonglong2 wa = *(const ulonglong2*)&Wd[kk][ty*8];
            ulonglong2 wb = *(const ulonglong2*)&Wd[kk][ty*8 + 4];
            ulonglong2 xa = *(const ulonglong2*)&Xs[kk][tx*4];
            ulonglong2 xb = *(const ulonglong2*)&Xs[kk][64 + tx*4];
            unsigned long long wp[4] = {wa.x, wa.y, wb.x, wb.y};
            unsigned long long xp[4] = {xa.x, xa.y, xb.x, xb.y};
#pragma unroll
            for (int i = 0; i < 4; i++) {
                FMA2(acc[i][0], wp[i], xp[0]);
                FMA2(acc[i][1], wp[i], xp[1]);
                FMA2(acc[i][2], wp[i], xp[2]);
                FMA2(acc[i][3], wp[i], xp[3]);
            }
        }
        __syncthreads();
    }

    // epilogue: store + stats
#pragma unroll
    for (int i = 0; i < 4; i++) {
        int r = row0 + ty*4 + i;
        float rs = 0.f, rq = 0.f;
        float v[8];
#pragma unroll
        for (int p = 0; p < 4; p++) {
            float lo, hi;
            asm("mov.b64 {%0, %1}, %2;" : "=f"(lo), "=f"(hi) : "l"(acc[i][p]));
            v[p*2] = lo; v[p*2+1] = hi;
            rs += lo + hi; rq += lo*lo + hi*hi;
        }
        *(float4*)&Yb[(size_t)r*NCOL + col0 + tx*4]      = make_float4(v[0], v[1], v[2], v[3]);
        *(float4*)&Yb[(size_t)r*NCOL + col0 + 64 + tx*4] = make_float4(v[4], v[5], v[6], v[7]);
        if (STATS) {
#pragma unroll
            for (int o = 8; o > 0; o >>= 1) {
                rs += __shfl_down_sync(0xffffffffu, rs, o);
                rq += __shfl_down_sync(0xffffffffu, rq, o);
            }
            if (tx == 0) { atomicAdd(&stats[r], rs); atomicAdd(&stats[Cout + r], rq); }
        }
    }
}

// ---------------- small GEMM (old style) for q,k projections (Cout=8) ----------------
template<int MODE, int STATS>
__global__ void k_gemm(const float* __restrict__ W, const float* __restrict__ X,
                       float* __restrict__ Y, int Cin, int Cout, int NCOL,
                       const float* __restrict__ sb, float* __restrict__ stats)
{
    const int b = blockIdx.z;
    const float* Xb = X + (size_t)b * Cin * NCOL;
    float* Yb = Y + (size_t)b * Cout * NCOL;
    const int col0 = blockIdx.x * 64;
    const int row0 = blockIdx.y * 64;
    __shared__ float Ws[16][68];
    __shared__ float Xs[16][68];
    const int tid = threadIdx.x;
    const int tx = tid & 15, ty = tid >> 4;
    float acc[4][4];
#pragma unroll
    for (int i = 0; i < 4; i++)
#pragma unroll
        for (int j = 0; j < 4; j++) acc[i][j] = 0.f;

    for (int k0 = 0; k0 < Cin; k0 += 16) {
        {
            int kk = tid & 15, r = tid >> 4;
#pragma unroll
            for (int i = 0; i < 4; i++) {
                int rr = r + i*16;
                float w = 0.f;
                if (row0+rr < Cout && k0+kk < Cin) w = W[(size_t)(row0+rr)*Cin + k0+kk];
                Ws[kk][rr] = w;
            }
            int col = tid & 63, c4 = tid >> 6;
#pragma unroll
            for (int i = 0; i < 4; i++) {
                int cc = c4 + i*4;
                float v = 0.f;
                int cg = k0 + cc, colg = col0 + col;
                if (cg < Cin && colg < NCOL) {
                    v = Xb[(size_t)cg*NCOL + colg];
                    if (MODE == 1) v = fmaxf(fmaf(v, sb[cg], sb[Cin+cg]), 0.f);
                }
                Xs[cc][col] = v;
            }
        }
        __syncthreads();
#pragma unroll
        for (int kk = 0; kk < 16; kk++) {
            float4 wv4 = *(const float4*)&Ws[kk][ty*4];
            float4 xv4 = *(const float4*)&Xs[kk][tx*4];
            float wv[4] = {wv4.x, wv4.y, wv4.z, wv4.w};
            float xv[4] = {xv4.x, xv4.y, xv4.z, xv4.w};
#pragma unroll
            for (int i = 0; i < 4; i++)
#pragma unroll
                for (int j = 0; j < 4; j++) acc[i][j] = fmaf(wv[i], xv[j], acc[i][j]);
        }
        __syncthreads();
    }

#pragma unroll
    for (int i = 0; i < 4; i++) {
        int r = row0 + ty*4 + i;
        if (r < Cout) {
#pragma unroll
            for (int j = 0; j < 4; j++) {
                int cidx = col0 + tx*4 + j;
                if (cidx < NCOL) Yb[(size_t)r*NCOL + cidx] = acc[i][j];
            }
        }
    }
}

// ---------------- BN finalize: stats -> (scale, bias) ----------------
__global__ void k_fin(const float* __restrict__ stats, const float* __restrict__ g,
                      const float* __restrict__ be, float* __restrict__ sb,
                      int Cc, float invcnt)
{
    int c = blockIdx.x * 64 + threadIdx.x;
    if (c >= Cc) return;
    float mu  = stats[c] * invcnt;
    float var = stats[Cc + c] * invcnt - mu*mu;
    float s = g[c] * rsqrtf(var + EPSBN);
    sb[c] = s;
    sb[Cc + c] = be[c] - mu * s;
}

// ---------------- ball query: first NSAMP indices (in order) within radius ----------------
__global__ void k_bq(const float* __restrict__ src, const float* __restrict__ ctr,
                     int* __restrict__ out, int NSRC)
{
    int gw = (blockIdx.x * blockDim.x + threadIdx.x) >> 5;
    int lane = threadIdx.x & 31;
    __shared__ int lists[8][NSAMP];
    int* list = lists[threadIdx.x >> 5];
    if (gw >= BB*MC) return;
    int b = gw / MC, m = gw % MC;
    float cx = ctr[((size_t)b*MC + m)*3 + 0];
    float cy = ctr[((size_t)b*MC + m)*3 + 1];
    float cz = ctr[((size_t)b*MC + m)*3 + 2];
    int count = 0;
    for (int base = 0; base < NSRC; base += 32) {
        int n = base + lane;
        bool ok = false;
        if (n < NSRC) {
            float dx = src[((size_t)b*NSRC + n)*3 + 0] - cx;
            float dy = src[((size_t)b*NSRC + n)*3 + 1] - cy;
            float dz = src[((size_t)b*NSRC + n)*3 + 2] - cz;
            ok = (dx*dx + dy*dy + dz*dz) < RAD2;
        }
        unsigned mk = __ballot_sync(0xffffffffu, ok);
        if (ok) {
            int pos = count + __popc(mk & ((1u << lane) - 1u));
            if (pos < NSAMP) list[pos] = n;
        }
        count += __popc(mk);
        if (count >= NSAMP) break;
    }
    __syncwarp();
    if (lane < NSAMP) {
        int v;
        if (count == 0) v = 0;
        else v = (lane < count) ? list[lane] : list[0];
        out[((size_t)b*MC + m)*NSAMP + lane] = v;
    }
}

// ---------------- new_features transpose with affine+relu: [b,c,n] -> [b,n,c] ----------------
__global__ void k_nft(const float* __restrict__ y3, const float* __restrict__ sb3,
                      float* __restrict__ nft)
{
    int b = blockIdx.z;
    int n0 = blockIdx.x * 32, c0 = blockIdx.y * 32;
    __shared__ float t[32][33];
#pragma unroll
    for (int i = 0; i < 4; i++) {
        int c = c0 + threadIdx.y + i*8;
        int n = n0 + threadIdx.x;
        float v = y3[((size_t)b*256 + c)*NPTS + n];
        v = fmaxf(fmaf(v, sb3[c], sb3[256 + c]), 0.f);
        t[threadIdx.y + i*8][threadIdx.x] = v;
    }
    __syncthreads();
#pragma unroll
    for (int i = 0; i < 4; i++) {
        int n = n0 + threadIdx.y + i*8;
        int c = c0 + threadIdx.x;
        nft[((size_t)b*NPTS + n)*256 + c] = t[threadIdx.x][threadIdx.y + i*8];
    }
}

// ---------------- build ip [b,259,slot,center]: gathered features + rel xyz ----------------
__global__ void k_ip(const float* __restrict__ nft, const int* __restrict__ idx1,
                     const int* __restrict__ idx2, const float* __restrict__ xyz,
                     const float* __restrict__ ctr, float* __restrict__ ip)
{
    int bz = blockIdx.x;
    int cblk = bz & 31;
    int slot = (bz >> 5) & 15;
    int b    = bz >> 9;
    __shared__ float s[256][33];
    int warp = threadIdx.x >> 5, lane = threadIdx.x & 31;
#pragma unroll
    for (int w = 0; w < 4; w++) {
        int center = cblk*32 + warp*4 + w;
        int id = idx1[((size_t)b*MC + center)*NSAMP + slot];
        const float* srcp = nft + ((size_t)b*NPTS + id)*256;
#pragma unroll
        for (int t = 0; t < 8; t++) s[lane + t*32][warp*4 + w] = srcp[lane + t*32];
    }
    __syncthreads();
    int center = threadIdx.x & 31, chb = threadIdx.x >> 5;
#pragma unroll
    for (int t = 0; t < 32; t++) {
        int ch = chb + t*8;
        ip[(((size_t)b*259 + ch)*NSAMP + slot)*MC + cblk*32 + center] = s[ch][center];
    }
    if (threadIdx.x < 96) {
        int d = threadIdx.x / 32;
        int cc = threadIdx.x & 31;
        int ctr_i = cblk*32 + cc;
        int i1 = idx1[((size_t)b*MC + ctr_i)*NSAMP + slot];
        int i2 = idx2[((size_t)b*MC + ctr_i)*NSAMP + slot];
        float r = ctr[((size_t)b*MC + i2)*3 + d] - xyz[((size_t)b*NPTS + i1)*3 + d];
        ip[(((size_t)b*259 + 256 + d)*NSAMP + slot)*MC + ctr_i] = r;
    }
}

// ---------------- attention logits + column softmax over n (one CTA per column j) --------
__global__ void k_att(const float* __restrict__ q, const float* __restrict__ k,
                      float* __restrict__ P)
{
    int bx = blockIdx.x;
    int j = bx & (MC-1);
    int slot = (bx >> 10) & 15;
    int b = bx >> 14;
    __shared__ float red[256];
    float qv[8];
#pragma unroll
    for (int c = 0; c < 8; c++)
        qv[c] = q[(((size_t)b*8 + c)*NSAMP + slot)*MC + j];
    const float* kb = k + ((size_t)b*8*NSAMP + slot)*MC;
    float s[4];
#pragma unroll
    for (int t = 0; t < 4; t++) {
        int n = threadIdx.x + t*256;
        float a = 0.f;
#pragma unroll
        for (int c = 0; c < 8; c++) a = fmaf(kb[(size_t)c*NSAMP*MC + n], qv[c], a);
        s[t] = a;
    }
    float mx = fmaxf(fmaxf(s[0], s[1]), fmaxf(s[2], s[3]));
    red[threadIdx.x] = mx; __syncthreads();
    for (int o = 128; o > 0; o >>= 1) {
        if (threadIdx.x < o) red[threadIdx.x] = fmaxf(red[threadIdx.x], red[threadIdx.x + o]);
        __syncthreads();
    }
    mx = red[0]; __syncthreads();
    float es[4]; float sum = 0.f;
#pragma unroll
    for (int t = 0; t < 4; t++) { es[t] = __expf(s[t] - mx); sum += es[t]; }
    red[threadIdx.x] = sum; __syncthreads();
    for (int o = 128; o > 0; o >>= 1) {
        if (threadIdx.x < o) red[threadIdx.x] += red[threadIdx.x + o];
        __syncthreads();
    }
    float inv = 1.f / red[0];
    float* Pb = P + (((size_t)(b*NSAMP + slot))*MC + j)*MC;
#pragma unroll
    for (int t = 0; t < 4; t++) Pb[threadIdx.x + t*256] = es[t] * inv;
}

// ======== att_feat = V * P^T (NT, packed f32x2), fused "- group_features" ========
// Tile: 64 c-rows x 128 j-cols, K = n (1024). V and P both n-contiguous.
__global__ void k_attfeat2(const float* __restrict__ V, const float* __restrict__ P,
                           const float* __restrict__ ip, float* __restrict__ off)
{
    int bs = blockIdx.z;
    int slot = bs & 15, b = bs >> 4;
    const float* Vb = V + ((size_t)b*256*NSAMP + slot)*MC;   // row c stride NSAMP*MC, n contiguous
    const float* Pb = P + ((size_t)(b*NSAMP + slot))*MC*MC;  // row j stride MC, n contiguous
    const int j0 = blockIdx.x * 128;
    const int c0 = blockIdx.y * 64;
    __shared__ float Vd[16][132];   // dup (v,v) over 64 c-rows
    __shared__ float Ps[16][132];   // 128 j-rows
    const int tid = threadIdx.x;
    const int tx = tid & 15, ty = tid >> 4;

    unsigned long long acc[4][4];
#pragma unroll
    for (int i = 0; i < 4; i++)
#pragma unroll
        for (int p = 0; p < 4; p++) acc[i][p] = 0ull;

    for (int n0 = 0; n0 < MC; n0 += 16) {
        // V tile: 64 rows x 16 kk; thread: row=tid>>2, f=tid&3 reads float4 along n
        {
            int row = tid >> 2, f = tid & 3;
            float4 v4 = *(const float4*)&Vb[(size_t)(c0+row)*NSAMP*MC + n0 + 4*f];
            float vv[4] = {v4.x, v4.y, v4.z, v4.w};
#pragma unroll
            for (int s2 = 0; s2 < 4; s2++)
                *(float2*)&Vd[4*f + s2][2*row] = make_float2(vv[s2], vv[s2]);
        }
        // P tile: 128 rows x 16 kk; two passes
        {
            int f = tid & 3;
#pragma unroll
            for (int p = 0; p < 2; p++) {
                int row = (tid >> 2) + 64*p;
                float4 p4 = *(const float4*)&Pb[(size_t)(j0+row)*MC + n0 + 4*f];
                float pv[4] = {p4.x, p4.y, p4.z, p4.w};
#pragma unroll
                for (int s2 = 0; s2 < 4; s2++) Ps[4*f + s2][row] = pv[s2];
            }
        }
        __syncthreads();
#pragma unroll
        for (int kk = 0; kk < 16; kk++) {
            ulonglong2 wa = *(const ulonglong2*)&Vd[kk][ty*8];
            ulonglong2 wb = *(const ulonglong2*)&Vd[kk][ty*8 + 4];
            ulonglong2 xa = *(const ulonglong2*)&Ps[kk][tx*4];
            ulonglong2 xb = *(const ulonglong2*)&Ps[kk][64 + tx*4];
            unsigned long long wp[4] = {wa.x, wa.y, wb.x, wb.y};
            unsigned long long xp[4] = {xa.x, xa.y, xb.x, xb.y};
#pragma unroll
            for (int i = 0; i < 4; i++) {
                FMA2(acc[i][0], wp[i], xp[0]);
                FMA2(acc[i][1], wp[i], xp[1]);
                FMA2(acc[i][2], wp[i], xp[2]);
                FMA2(acc[i][3], wp[i], xp[3]);
            }
        }
        __syncthreads();
    }

#pragma unroll
    for (int i = 0; i < 4; i++) {
        int c = c0 + ty*4 + i;
        const float* ipr = ip + (((size_t)b*259 + c)*NSAMP + slot)*MC;
        float* offr = off + (((size_t)b*256 + c)*NSAMP + slot)*MC;
        float v[8];
#pragma unroll
        for (int p = 0; p < 4; p++) {
            float lo, hi;
            asm("mov.b64 {%0, %1}, %2;" : "=f"(lo), "=f"(hi) : "l"(acc[i][p]));
            v[p*2] = lo; v[p*2+1] = hi;
        }
        {
            int jj = j0 + tx*4;
            float4 g4 = *(const float4*)&ipr[jj];
            *(float4*)&offr[jj] = make_float4(v[0]-g4.x, v[1]-g4.y, v[2]-g4.z, v[3]-g4.w);
        }
        {
            int jj = j0 + 64 + tx*4;
            float4 g4 = *(const float4*)&ipr[jj];
            *(float4*)&offr[jj] = make_float4(v[4]-g4.x, v[5]-g4.y, v[6]-g4.z, v[7]-g4.w);
        }
    }
}

// ---------------- relu(affine(yf)) + gf residual, max-pool over slot ----------------
__global__ void k_pool(const float* __restrict__ yf, const float* __restrict__ sbf,
                       const float* __restrict__ ip, float* __restrict__ pool)
{
    int i = blockIdx.x * 256 + threadIdx.x;
    if (i >= BB*256*MC) return;
    int center = i & (MC-1);
    int c = (i >> 10) & 255;
    int b = i >> 18;
    float s = sbf[c], bi = sbf[256 + c];
    float mx = -1e30f;
#pragma unroll
    for (int slot = 0; slot < NSAMP; slot++) {
        float v = fmaxf(fmaf(yf[(((size_t)b*256 + c)*NSAMP + slot)*MC + center], s, bi), 0.f);
        v += ip[(((size_t)b*259 + c)*NSAMP + slot)*MC + center];
        mx = fmaxf(mx, v);
    }
    pool[((size_t)b*256 + c)*MC + center] = mx;
}

// ---------------- final: out = [ctr_xyz (optional), relu(affine(yo))] ----------------
__global__ void k_final(const float* __restrict__ yo, const float* __restrict__ sbo,
                        const float* __restrict__ ctr, float* __restrict__ out, int has_ctr)
{
    int off0 = has_ctr ? BB*MC*3 : 0;
    int total = off0 + BB*512*MC;
    int i = blockIdx.x * 256 + threadIdx.x;
    if (i >= total) return;
    if (i < off0) { out[i] = ctr[i]; return; }
    int j = i - off0;
    int ch = (j >> 10) & 511;
    out[i] = fmaxf(fmaf(yo[j], sbo[ch], sbo[512 + ch]), 0.f);
}

// ---------------- host launch ----------------
extern "C" void kernel_launch(void* const* d_in, const int* in_sizes, int n_in,
                              void* d_out, int out_size)
{
    const float* xyz   = (const float*)d_in[0];
    const float* feats = (const float*)d_in[1];
    const float* ctr   = (const float*)d_in[2];
    const float* W1 = (const float*)d_in[3];
    const float* g1 = (const float*)d_in[4];
    const float* b1 = (const float*)d_in[5];
    const float* W2 = (const float*)d_in[6];
    const float* g2 = (const float*)d_in[7];
    const float* b2 = (const float*)d_in[8];
    const float* W3 = (const float*)d_in[9];
    const float* g3 = (const float*)d_in[10];
    const float* b3 = (const float*)d_in[11];
    const float* Wq = (const float*)d_in[12];
    const float* Wk = (const float*)d_in[13];
    const float* Wv = (const float*)d_in[14];
    const float* Wf = (const float*)d_in[15];
    const float* gp = (const float*)d_in[16];
    const float* bp = (const float*)d_in[17];
    const float* Wo = (const float*)d_in[18];
    const float* go = (const float*)d_in[19];
    const float* bo = (const float*)d_in[20];
    float* outp = (float*)d_out;

    float *featin, *y1, *y2, *y3, *nft, *ip, *qb, *kb, *vb, *Pb, *offb, *yf, *pool, *yo;
    int *idx1, *idx2;
    float *st1, *st2, *st3, *stf, *sto, *sb1, *sb2, *sb3, *sbf, *sbo;
    cudaGetSymbolAddress((void**)&featin, g_featin);
    cudaGetSymbolAddress((void**)&y1, g_y1);
    cudaGetSymbolAddress((void**)&y2, g_y2);
    cudaGetSymbolAddress((void**)&y3, g_y3);
    cudaGetSymbolAddress((void**)&nft, g_nft);
    cudaGetSymbolAddress((void**)&idx1, g_idx1);
    cudaGetSymbolAddress((void**)&idx2, g_idx2);
    cudaGetSymbolAddress((void**)&ip, g_ip);
    cudaGetSymbolAddress((void**)&qb, g_q);
    cudaGetSymbolAddress((void**)&kb, g_k);
    cudaGetSymbolAddress((void**)&vb, g_v);
    cudaGetSymbolAddress((void**)&Pb, g_P);
    cudaGetSymbolAddress((void**)&offb, g_off);
    cudaGetSymbolAddress((void**)&yf, g_yf);
    cudaGetSymbolAddress((void**)&pool, g_pool);
    cudaGetSymbolAddress((void**)&yo, g_yo);
    cudaGetSymbolAddress((void**)&st1, g_st1);
    cudaGetSymbolAddress((void**)&st2, g_st2);
    cudaGetSymbolAddress((void**)&st3, g_st3);
    cudaGetSymbolAddress((void**)&stf, g_stf);
    cudaGetSymbolAddress((void**)&sto, g_sto);
    cudaGetSymbolAddress((void**)&sb1, g_sb1);
    cudaGetSymbolAddress((void**)&sb2, g_sb2);
    cudaGetSymbolAddress((void**)&sb3, g_sb3);
    cudaGetSymbolAddress((void**)&sbf, g_sbf);
    cudaGetSymbolAddress((void**)&sbo, g_sbo);

    cudaMemsetAsync(st1, 0, sizeof(float)*2*64,  0);
    cudaMemsetAsync(st2, 0, sizeof(float)*2*128, 0);
    cudaMemsetAsync(st3, 0, sizeof(float)*2*256, 0);
    cudaMemsetAsync(stf, 0, sizeof(float)*2*256, 0);
    cudaMemsetAsync(sto, 0, sizeof(float)*2*512, 0);

    // stage 0: concat input
    k_featin<<<(BB*67*NPTS + 255)/256, 256>>>(xyz, feats, featin);

    // MLP stages (packed f32x2) with batch-stats BN folded into next stage
    k_gemm2<0,1><<<dim3(NPTS/128, 1, BB), 256>>>(W1, featin, y1, 67, 64, NPTS, nullptr, st1);
    k_fin<<<1, 64>>>(st1, g1, b1, sb1, 64, 1.f/(BB*NPTS));
    k_gemm2<1,1><<<dim3(NPTS/128, 2, BB), 256>>>(W2, y1, y2, 64, 128, NPTS, sb1, st2);
    k_fin<<<2, 64>>>(st2, g2, b2, sb2, 128, 1.f/(BB*NPTS));
    k_gemm2<1,1><<<dim3(NPTS/128, 4, BB), 256>>>(W3, y2, y3, 128, 256, NPTS, sb2, st3);
    k_fin<<<4, 64>>>(st3, g3, b3, sb3, 256, 1.f/(BB*NPTS));

    // new_features transposed to n-major (coalesced gathers)
    k_nft<<<dim3(NPTS/32, 8, BB), dim3(32, 8)>>>(y3, sb3, nft);

    // ball queries
    k_bq<<<(BB*MC*32 + 255)/256, 256>>>(xyz, ctr, idx1, NPTS);
    k_bq<<<(BB*MC*32 + 255)/256, 256>>>(ctr, ctr, idx2, MC);

    // gather ip = [group_features ; rel]
    k_ip<<<BB*16*32, 256>>>(nft, idx1, idx2, xyz, ctr, ip);

    // q, k, v projections
    k_gemm<0,0><<<dim3(256, 1, BB), 256>>>(Wq, ip, qb, 259, 8,   MC*NSAMP, nullptr, nullptr);
    k_gemm<0,0><<<dim3(256, 1, BB), 256>>>(Wk, ip, kb, 259, 8,   MC*NSAMP, nullptr, nullptr);
    k_gemm2<0,0><<<dim3(128, 4, BB), 256>>>(Wv, ip, vb, 259, 256, MC*NSAMP, nullptr, nullptr);

    // attention: logits + softmax over n, then att_feat = V P^T fused with -gf
    k_att<<<BB*NSAMP*MC, 256>>>(qb, kb, Pb);
    k_attfeat2<<<dim3(8, 4, BB*NSAMP), 256>>>(vb, Pb, ip, offb);

    // Wf + BN stats, pool (affine+relu+residual+max over slot)
    k_gemm2<0,1><<<dim3(128, 4, BB), 256>>>(Wf, offb, yf, 256, 256, MC*NSAMP, nullptr, stf);
    k_fin<<<4, 64>>>(stf, gp, bp, sbf, 256, 1.f/(BB*MC*NSAMP));
    k_pool<<<(BB*256*MC + 255)/256, 256>>>(yf, sbf, ip, pool);

    // output conv + BN
    k_gemm2<0,1><<<dim3(MC/128, 8, BB), 256>>>(Wo, pool, yo, 256, 512, MC, nullptr, sto);
    k_fin<<<8, 64>>>(sto, go, bo, sbo, 512, 1.f/(BB*MC));

    int has_ctr = (out_size == BB*MC*3 + BB*512*MC) ? 1 : 0;
    int total = (has_ctr ? BB*MC*3 : 0) + BB*512*MC;
    k_final<<<(total + 255)/256, 256>>>(yo, sbo, ctr, outp, has_ctr);
}

// round 4
// speedup vs baseline: 1.0610x; 1.0589x over previous
#include <cuda_runtime.h>

// ---------------- problem constants ----------------
#define BB    4
#define NPTS  8192
#define MC    1024
#define NSAMP 16
#define CFEAT 64
#define RAD2  0.25f
#define EPSBN 1e-5f

#define FMA2(acc, a, b) asm("fma.rn.f32x2 %0, %1, %2, %0;" : "+l"(acc) : "l"(a), "l"(b))

// ---------------- scratch (__device__ globals; no runtime alloc) ----------------
static __device__ float g_featin[(size_t)BB*67*NPTS];
static __device__ float g_y1[(size_t)BB*64*NPTS];
static __device__ float g_y2[(size_t)BB*128*NPTS];
static __device__ float g_y3[(size_t)BB*256*NPTS];
static __device__ float g_nft[(size_t)BB*NPTS*256];
static __device__ int   g_idx1[BB*MC*NSAMP];
static __device__ int   g_idx2[BB*MC*NSAMP];
static __device__ float g_ip[(size_t)BB*259*MC*NSAMP];
static __device__ float g_q[(size_t)BB*8*MC*NSAMP];
static __device__ float g_k[(size_t)BB*8*MC*NSAMP];
static __device__ float g_v[(size_t)BB*256*MC*NSAMP];
static __device__ float g_P[(size_t)BB*NSAMP*MC*MC];
static __device__ float g_off[(size_t)BB*256*MC*NSAMP];
static __device__ float g_yf[(size_t)BB*256*MC*NSAMP];
static __device__ float g_pool[(size_t)BB*256*MC];
static __device__ float g_yo[(size_t)BB*512*MC];
static __device__ float g_st1[2*64], g_st2[2*128], g_st3[2*256], g_stf[2*256], g_sto[2*512];
static __device__ float g_sb1[2*64], g_sb2[2*128], g_sb3[2*256], g_sbf[2*256], g_sbo[2*512];

// ---------------- build concat(xyz^T, features) ----------------
__global__ void k_featin(const float* __restrict__ xyz, const float* __restrict__ feats,
                         float* __restrict__ out)
{
    int i = blockIdx.x * 256 + threadIdx.x;
    if (i >= BB*67*NPTS) return;
    int n  = i % NPTS;
    int ch = (i / NPTS) % 67;
    int b  = i / (NPTS*67);
    float v;
    if (ch < 3) v = xyz[((size_t)b*NPTS + n)*3 + ch];
    else        v = feats[((size_t)b*CFEAT + (ch-3))*NPTS + n];
    out[i] = v;
}

// ======== packed-f32x2 GEMM, double-buffered: Y[b,o,col] = sum_c W[o,c]*f(X[b,c,col]) ====
// Tile 64 rows x 128 cols, 256 threads, per-thread 4 rows x 8 cols, K-chunk 16.
// Requires Cout % 64 == 0, NCOL % 128 == 0.
template<int MODE, int STATS>
__global__ void __launch_bounds__(256, 2)
k_gemm2(const float* __restrict__ W, const float* __restrict__ X,
        float* __restrict__ Y, int Cin, int Cout, int NCOL,
        const float* __restrict__ sb, float* __restrict__ stats)
{
    const int b = blockIdx.z;
    const float* Xb = X + (size_t)b * Cin * NCOL;
    float* Yb = Y + (size_t)b * Cout * NCOL;
    const int col0 = blockIdx.x * 128;
    const int row0 = blockIdx.y * 64;
    __shared__ float Wd[2][16][132];
    __shared__ float Xs[2][16][132];
    const int tid = threadIdx.x;
    const int tx = tid & 15, ty = tid >> 4;

    const int wkk = tid & 15, wrb = tid >> 4;       // W load: col wkk, rows wrb+16p
    const int xcol = tid & 127, xkb = tid >> 7;     // X load: col xcol, kk = xkb+2t

    float wreg[4];
    float xreg[8];
    const int nch = (Cin + 15) >> 4;

    // prefetch chunk 0
    {
        int k0 = 0;
#pragma unroll
        for (int p = 0; p < 4; p++) {
            float w = 0.f;
            if (k0 + wkk < Cin) w = W[(size_t)(row0 + wrb + 16*p)*Cin + k0 + wkk];
            wreg[p] = w;
        }
#pragma unroll
        for (int t = 0; t < 8; t++) {
            int cg = k0 + xkb + 2*t;
            float v = 0.f;
            if (cg < Cin) {
                v = Xb[(size_t)cg*NCOL + col0 + xcol];
                if (MODE == 1) v = fmaxf(fmaf(v, sb[cg], sb[Cin+cg]), 0.f);
            }
            xreg[t] = v;
        }
    }
    // store chunk 0
#pragma unroll
    for (int p = 0; p < 4; p++) *(float2*)&Wd[0][wkk][2*(wrb+16*p)] = make_float2(wreg[p], wreg[p]);
#pragma unroll
    for (int t = 0; t < 8; t++) Xs[0][xkb + 2*t][xcol] = xreg[t];
    __syncthreads();

    unsigned long long acc[4][4];
#pragma unroll
    for (int i = 0; i < 4; i++)
#pragma unroll
        for (int p = 0; p < 4; p++) acc[i][p] = 0ull;

    for (int c = 0; c < nch; c++) {
        int buf = c & 1;
        if (c + 1 < nch) {
            int k0 = (c + 1) << 4;
#pragma unroll
            for (int p = 0; p < 4; p++) {
                float w = 0.f;
                if (k0 + wkk < Cin) w = W[(size_t)(row0 + wrb + 16*p)*Cin + k0 + wkk];
                wreg[p] = w;
            }
#pragma unroll
            for (int t = 0; t < 8; t++) {
                int cg = k0 + xkb + 2*t;
                float v = 0.f;
                if (cg < Cin) {
                    v = Xb[(size_t)cg*NCOL + col0 + xcol];
                    if (MODE == 1) v = fmaxf(fmaf(v, sb[cg], sb[Cin+cg]), 0.f);
                }
                xreg[t] = v;
            }
        }
#pragma unroll
        for (int kk = 0; kk < 16; kk++) {
            ulonglong2 wa = *(const ulonglong2*)&Wd[buf][kk][ty*8];
            ulonglong2 wb = *(const ulonglong2*)&Wd[buf][kk][ty*8 + 4];
            ulonglong2 xa = *(const ulonglong2*)&Xs[buf][kk][tx*4];
            ulonglong2 xb = *(const ulonglong2*)&Xs[buf][kk][64 + tx*4];
            unsigned long long wp[4] = {wa.x, wa.y, wb.x, wb.y};
            unsigned long long xp[4] = {xa.x, xa.y, xb.x, xb.y};
#pragma unroll
            for (int i = 0; i < 4; i++) {
                FMA2(acc[i][0], wp[i], xp[0]);
                FMA2(acc[i][1], wp[i], xp[1]);
                FMA2(acc[i][2], wp[i], xp[2]);
                FMA2(acc[i][3], wp[i], xp[3]);
            }
        }
        if (c + 1 < nch) {
            int nb = buf ^ 1;
#pragma unroll
            for (int p = 0; p < 4; p++) *(float2*)&Wd[nb][wkk][2*(wrb+16*p)] = make_float2(wreg[p], wreg[p]);
#pragma unroll
            for (int t = 0; t < 8; t++) Xs[nb][xkb + 2*t][xcol] = xreg[t];
            __syncthreads();
        }
    }

    // epilogue: store + stats
#pragma unroll
    for (int i = 0; i < 4; i++) {
        int r = row0 + ty*4 + i;
        float rs = 0.f, rq = 0.f;
        float v[8];
#pragma unroll
        for (int p = 0; p < 4; p++) {
            float lo, hi;
            asm("mov.b64 {%0, %1}, %2;" : "=f"(lo), "=f"(hi) : "l"(acc[i][p]));
            v[p*2] = lo; v[p*2+1] = hi;
            rs += lo + hi; rq += lo*lo + hi*hi;
        }
        *(float4*)&Yb[(size_t)r*NCOL + col0 + tx*4]      = make_float4(v[0], v[1], v[2], v[3]);
        *(float4*)&Yb[(size_t)r*NCOL + col0 + 64 + tx*4] = make_float4(v[4], v[5], v[6], v[7]);
        if (STATS) {
#pragma unroll
            for (int o = 8; o > 0; o >>= 1) {
                rs += __shfl_down_sync(0xffffffffu, rs, o);
                rq += __shfl_down_sync(0xffffffffu, rq, o);
            }
            if (tx == 0) { atomicAdd(&stats[r], rs); atomicAdd(&stats[Cout + r], rq); }
        }
    }
}

// ---------------- fused q+k projection: 16 output rows, no wasted tiles ----------------
__global__ void k_qk(const float* __restrict__ Wq, const float* __restrict__ Wk,
                     const float* __restrict__ X, float* __restrict__ q,
                     float* __restrict__ k)
{
    const int b = blockIdx.y;
    const int NCOL = MC*NSAMP;
    const float* Xb = X + (size_t)b * 259 * NCOL;
    __shared__ float Ws[16][260];
    for (int i = threadIdx.x; i < 8*259; i += 128) {
        int r = i / 259, c = i % 259;
        Ws[r][c] = Wq[i];
        Ws[r+8][c] = Wk[i];
    }
    __syncthreads();
    int col = blockIdx.x * 128 + threadIdx.x;
    float acc[16];
#pragma unroll
    for (int o = 0; o < 16; o++) acc[o] = 0.f;
    for (int c = 0; c < 259; c++) {
        float xv = Xb[(size_t)c*NCOL + col];
#pragma unroll
        for (int o = 0; o < 16; o++) acc[o] = fmaf(Ws[o][c], xv, acc[o]);
    }
#pragma unroll
    for (int o = 0; o < 8; o++) {
        q[((size_t)b*8 + o)*NCOL + col] = acc[o];
        k[((size_t)b*8 + o)*NCOL + col] = acc[o+8];
    }
}

// ---------------- BN finalize: stats -> (scale, bias) ----------------
__global__ void k_fin(const float* __restrict__ stats, const float* __restrict__ g,
                      const float* __restrict__ be, float* __restrict__ sb,
                      int Cc, float invcnt)
{
    int c = blockIdx.x * 64 + threadIdx.x;
    if (c >= Cc) return;
    float mu  = stats[c] * invcnt;
    float var = stats[Cc + c] * invcnt - mu*mu;
    float s = g[c] * rsqrtf(var + EPSBN);
    sb[c] = s;
    sb[Cc + c] = be[c] - mu * s;
}

// ---------------- ball query: first NSAMP indices (in order) within radius ----------------
__global__ void k_bq(const float* __restrict__ src, const float* __restrict__ ctr,
                     int* __restrict__ out, int NSRC)
{
    int gw = (blockIdx.x * blockDim.x + threadIdx.x) >> 5;
    int lane = threadIdx.x & 31;
    __shared__ int lists[8][NSAMP];
    int* list = lists[threadIdx.x >> 5];
    if (gw >= BB*MC) return;
    int b = gw / MC, m = gw % MC;
    float cx = ctr[((size_t)b*MC + m)*3 + 0];
    float cy = ctr[((size_t)b*MC + m)*3 + 1];
    float cz = ctr[((size_t)b*MC + m)*3 + 2];
    int count = 0;
    for (int base = 0; base < NSRC; base += 32) {
        int n = base + lane;
        bool ok = false;
        if (n < NSRC) {
            float dx = src[((size_t)b*NSRC + n)*3 + 0] - cx;
            float dy = src[((size_t)b*NSRC + n)*3 + 1] - cy;
            float dz = src[((size_t)b*NSRC + n)*3 + 2] - cz;
            ok = (dx*dx + dy*dy + dz*dz) < RAD2;
        }
        unsigned mk = __ballot_sync(0xffffffffu, ok);
        if (ok) {
            int pos = count + __popc(mk & ((1u << lane) - 1u));
            if (pos < NSAMP) list[pos] = n;
        }
        count += __popc(mk);
        if (count >= NSAMP) break;
    }
    __syncwarp();
    if (lane < NSAMP) {
        int v;
        if (count == 0) v = 0;
        else v = (lane < count) ? list[lane] : list[0];
        out[((size_t)b*MC + m)*NSAMP + lane] = v;
    }
}

// ---------------- new_features transpose with affine+relu: [b,c,n] -> [b,n,c] ----------------
__global__ void k_nft(const float* __restrict__ y3, const float* __restrict__ sb3,
                      float* __restrict__ nft)
{
    int b = blockIdx.z;
    int n0 = blockIdx.x * 32, c0 = blockIdx.y * 32;
    __shared__ float t[32][33];
#pragma unroll
    for (int i = 0; i < 4; i++) {
        int c = c0 + threadIdx.y + i*8;
        int n = n0 + threadIdx.x;
        float v = y3[((size_t)b*256 + c)*NPTS + n];
        v = fmaxf(fmaf(v, sb3[c], sb3[256 + c]), 0.f);
        t[threadIdx.y + i*8][threadIdx.x] = v;
    }
    __syncthreads();
#pragma unroll
    for (int i = 0; i < 4; i++) {
        int n = n0 + threadIdx.y + i*8;
        int c = c0 + threadIdx.x;
        nft[((size_t)b*NPTS + n)*256 + c] = t[threadIdx.x][threadIdx.y + i*8];
    }
}

// ---------------- build ip [b,259,slot,center]: gathered features + rel xyz ----------------
__global__ void k_ip(const float* __restrict__ nft, const int* __restrict__ idx1,
                     const int* __restrict__ idx2, const float* __restrict__ xyz,
                     const float* __restrict__ ctr, float* __restrict__ ip)
{
    int bz = blockIdx.x;
    int cblk = bz & 31;
    int slot = (bz >> 5) & 15;
    int b    = bz >> 9;
    __shared__ float s[256][33];
    int warp = threadIdx.x >> 5, lane = threadIdx.x & 31;
#pragma unroll
    for (int w = 0; w < 4; w++) {
        int center = cblk*32 + warp*4 + w;
        int id = idx1[((size_t)b*MC + center)*NSAMP + slot];
        const float* srcp = nft + ((size_t)b*NPTS + id)*256;
#pragma unroll
        for (int t = 0; t < 8; t++) s[lane + t*32][warp*4 + w] = srcp[lane + t*32];
    }
    __syncthreads();
    int center = threadIdx.x & 31, chb = threadIdx.x >> 5;
#pragma unroll
    for (int t = 0; t < 32; t++) {
        int ch = chb + t*8;
        ip[(((size_t)b*259 + ch)*NSAMP + slot)*MC + cblk*32 + center] = s[ch][center];
    }
    if (threadIdx.x < 96) {
        int d = threadIdx.x / 32;
        int cc = threadIdx.x & 31;
        int ctr_i = cblk*32 + cc;
        int i1 = idx1[((size_t)b*MC + ctr_i)*NSAMP + slot];
        int i2 = idx2[((size_t)b*MC + ctr_i)*NSAMP + slot];
        float r = ctr[((size_t)b*MC + i2)*3 + d] - xyz[((size_t)b*NPTS + i1)*3 + d];
        ip[(((size_t)b*259 + 256 + d)*NSAMP + slot)*MC + ctr_i] = r;
    }
}

// ---------------- attention logits + column softmax over n (one CTA per column j) --------
__global__ void k_att(const float* __restrict__ q, const float* __restrict__ k,
                      float* __restrict__ P)
{
    int bx = blockIdx.x;
    int j = bx & (MC-1);
    int slot = (bx >> 10) & 15;
    int b = bx >> 14;
    __shared__ float red[256];
    float qv[8];
#pragma unroll
    for (int c = 0; c < 8; c++)
        qv[c] = q[(((size_t)b*8 + c)*NSAMP + slot)*MC + j];
    const float* kb = k + ((size_t)b*8*NSAMP + slot)*MC;
    float s[4];
#pragma unroll
    for (int t = 0; t < 4; t++) {
        int n = threadIdx.x + t*256;
        float a = 0.f;
#pragma unroll
        for (int c = 0; c < 8; c++) a = fmaf(kb[(size_t)c*NSAMP*MC + n], qv[c], a);
        s[t] = a;
    }
    float mx = fmaxf(fmaxf(s[0], s[1]), fmaxf(s[2], s[3]));
    red[threadIdx.x] = mx; __syncthreads();
    for (int o = 128; o > 0; o >>= 1) {
        if (threadIdx.x < o) red[threadIdx.x] = fmaxf(red[threadIdx.x], red[threadIdx.x + o]);
        __syncthreads();
    }
    mx = red[0]; __syncthreads();
    float es[4]; float sum = 0.f;
#pragma unroll
    for (int t = 0; t < 4; t++) { es[t] = __expf(s[t] - mx); sum += es[t]; }
    red[threadIdx.x] = sum; __syncthreads();
    for (int o = 128; o > 0; o >>= 1) {
        if (threadIdx.x < o) red[threadIdx.x] += red[threadIdx.x + o];
        __syncthreads();
    }
    float inv = 1.f / red[0];
    float* Pb = P + (((size_t)(b*NSAMP + slot))*MC + j)*MC;
#pragma unroll
    for (int t = 0; t < 4; t++) Pb[threadIdx.x + t*256] = es[t] * inv;
}

// ======== att_feat = V * P^T (NT, packed f32x2, double-buffered), fused "-gf" ========
__global__ void __launch_bounds__(256, 2)
k_attfeat2(const float* __restrict__ V, const float* __restrict__ P,
           const float* __restrict__ ip, float* __restrict__ off)
{
    int bs = blockIdx.z;
    int slot = bs & 15, b = bs >> 4;
    const float* Vb = V + ((size_t)b*256*NSAMP + slot)*MC;
    const float* Pb = P + ((size_t)(b*NSAMP + slot))*MC*MC;
    const int j0 = blockIdx.x * 128;
    const int c0 = blockIdx.y * 64;
    __shared__ float Vd[2][16][132];
    __shared__ float Ps[2][16][132];
    const int tid = threadIdx.x;
    const int tx = tid & 15, ty = tid >> 4;
    const int vrow = tid >> 2, vf = tid & 3;

    float4 vreg, preg0, preg1;
    // prefetch chunk 0
    vreg  = *(const float4*)&Vb[(size_t)(c0+vrow)*NSAMP*MC + 4*vf];
    preg0 = *(const float4*)&Pb[(size_t)(j0+vrow)*MC + 4*vf];
    preg1 = *(const float4*)&Pb[(size_t)(j0+vrow+64)*MC + 4*vf];
    {
        float vv[4] = {vreg.x, vreg.y, vreg.z, vreg.w};
        float p0[4] = {preg0.x, preg0.y, preg0.z, preg0.w};
        float p1[4] = {preg1.x, preg1.y, preg1.z, preg1.w};
#pragma unroll
        for (int s2 = 0; s2 < 4; s2++) {
            *(float2*)&Vd[0][4*vf + s2][2*vrow] = make_float2(vv[s2], vv[s2]);
            Ps[0][4*vf + s2][vrow] = p0[s2];
            Ps[0][4*vf + s2][vrow + 64] = p1[s2];
        }
    }
    __syncthreads();

    unsigned long long acc[4][4];
#pragma unroll
    for (int i = 0; i < 4; i++)
#pragma unroll
        for (int p = 0; p < 4; p++) acc[i][p] = 0ull;

    const int nch = MC / 16;
    for (int c = 0; c < nch; c++) {
        int buf = c & 1;
        if (c + 1 < nch) {
            int n0 = (c + 1) << 4;
            vreg  = *(const float4*)&Vb[(size_t)(c0+vrow)*NSAMP*MC + n0 + 4*vf];
            preg0 = *(const float4*)&Pb[(size_t)(j0+vrow)*MC + n0 + 4*vf];
            preg1 = *(const float4*)&Pb[(size_t)(j0+vrow+64)*MC + n0 + 4*vf];
        }
#pragma unroll
        for (int kk = 0; kk < 16; kk++) {
            ulonglong2 wa = *(const ulonglong2*)&Vd[buf][kk][ty*8];
            ulonglong2 wb = *(const ulonglong2*)&Vd[buf][kk][ty*8 + 4];
            ulonglong2 xa = *(const ulonglong2*)&Ps[buf][kk][tx*4];
            ulonglong2 xb = *(const ulonglong2*)&Ps[buf][kk][64 + tx*4];
            unsigned long long wp[4] = {wa.x, wa.y, wb.x, wb.y};
            unsigned long long xp[4] = {xa.x, xa.y, xb.x, xb.y};
#pragma unroll
            for (int i = 0; i < 4; i++) {
                FMA2(acc[i][0], wp[i], xp[0]);
                FMA2(acc[i][1], wp[i], xp[1]);
                FMA2(acc[i][2], wp[i], xp[2]);
                FMA2(acc[i][3], wp[i], xp[3]);
            }
        }
        if (c + 1 < nch) {
            int nb = buf ^ 1;
            float vv[4] = {vreg.x, vreg.y, vreg.z, vreg.w};
            float p0[4] = {preg0.x, preg0.y, preg0.z, preg0.w};
            float p1[4] = {preg1.x, preg1.y, preg1.z, preg1.w};
#pragma unroll
            for (int s2 = 0; s2 < 4; s2++) {
                *(float2*)&Vd[nb][4*vf + s2][2*vrow] = make_float2(vv[s2], vv[s2]);
                Ps[nb][4*vf + s2][vrow] = p0[s2];
                Ps[nb][4*vf + s2][vrow + 64] = p1[s2];
            }
            __syncthreads();
        }
    }

#pragma unroll
    for (int i = 0; i < 4; i++) {
        int c = c0 + ty*4 + i;
        const float* ipr = ip + (((size_t)b*259 + c)*NSAMP + slot)*MC;
        float* offr = off + (((size_t)b*256 + c)*NSAMP + slot)*MC;
        float v[8];
#pragma unroll
        for (int p = 0; p < 4; p++) {
            float lo, hi;
            asm("mov.b64 {%0, %1}, %2;" : "=f"(lo), "=f"(hi) : "l"(acc[i][p]));
            v[p*2] = lo; v[p*2+1] = hi;
        }
        {
            int jj = j0 + tx*4;
            float4 g4 = *(const float4*)&ipr[jj];
            *(float4*)&offr[jj] = make_float4(v[0]-g4.x, v[1]-g4.y, v[2]-g4.z, v[3]-g4.w);
        }
        {
            int jj = j0 + 64 + tx*4;
            float4 g4 = *(const float4*)&ipr[jj];
            *(float4*)&offr[jj] = make_float4(v[4]-g4.x, v[5]-g4.y, v[6]-g4.z, v[7]-g4.w);
        }
    }
}

// ---------------- relu(affine(yf)) + gf residual, max-pool over slot ----------------
__global__ void k_pool(const float* __restrict__ yf, const float* __restrict__ sbf,
                       const float* __restrict__ ip, float* __restrict__ pool)
{
    int i = blockIdx.x * 256 + threadIdx.x;
    if (i >= BB*256*MC) return;
    int center = i & (MC-1);
    int c = (i >> 10) & 255;
    int b = i >> 18;
    float s = sbf[c], bi = sbf[256 + c];
    float mx = -1e30f;
#pragma unroll
    for (int slot = 0; slot < NSAMP; slot++) {
        float v = fmaxf(fmaf(yf[(((size_t)b*256 + c)*NSAMP + slot)*MC + center], s, bi), 0.f);
        v += ip[(((size_t)b*259 + c)*NSAMP + slot)*MC + center];
        mx = fmaxf(mx, v);
    }
    pool[((size_t)b*256 + c)*MC + center] = mx;
}

// ---------------- final: out = [ctr_xyz (optional), relu(affine(yo))] ----------------
__global__ void k_final(const float* __restrict__ yo, const float* __restrict__ sbo,
                        const float* __restrict__ ctr, float* __restrict__ out, int has_ctr)
{
    int off0 = has_ctr ? BB*MC*3 : 0;
    int total = off0 + BB*512*MC;
    int i = blockIdx.x * 256 + threadIdx.x;
    if (i >= total) return;
    if (i < off0) { out[i] = ctr[i]; return; }
    int j = i - off0;
    int ch = (j >> 10) & 511;
    out[i] = fmaxf(fmaf(yo[j], sbo[ch], sbo[512 + ch]), 0.f);
}

// ---------------- host launch ----------------
extern "C" void kernel_launch(void* const* d_in, const int* in_sizes, int n_in,
                              void* d_out, int out_size)
{
    const float* xyz   = (const float*)d_in[0];
    const float* feats = (const float*)d_in[1];
    const float* ctr   = (const float*)d_in[2];
    const float* W1 = (const float*)d_in[3];
    const float* g1 = (const float*)d_in[4];
    const float* b1 = (const float*)d_in[5];
    const float* W2 = (const float*)d_in[6];
    const float* g2 = (const float*)d_in[7];
    const float* b2 = (const float*)d_in[8];
    const float* W3 = (const float*)d_in[9];
    const float* g3 = (const float*)d_in[10];
    const float* b3 = (const float*)d_in[11];
    const float* Wq = (const float*)d_in[12];
    const float* Wk = (const float*)d_in[13];
    const float* Wv = (const float*)d_in[14];
    const float* Wf = (const float*)d_in[15];
    const float* gp = (const float*)d_in[16];
    const float* bp = (const float*)d_in[17];
    const float* Wo = (const float*)d_in[18];
    const float* go = (const float*)d_in[19];
    const float* bo = (const float*)d_in[20];
    float* outp = (float*)d_out;

    float *featin, *y1, *y2, *y3, *nft, *ip, *qb, *kb, *vb, *Pb, *offb, *yf, *pool, *yo;
    int *idx1, *idx2;
    float *st1, *st2, *st3, *stf, *sto, *sb1, *sb2, *sb3, *sbf, *sbo;
    cudaGetSymbolAddress((void**)&featin, g_featin);
    cudaGetSymbolAddress((void**)&y1, g_y1);
    cudaGetSymbolAddress((void**)&y2, g_y2);
    cudaGetSymbolAddress((void**)&y3, g_y3);
    cudaGetSymbolAddress((void**)&nft, g_nft);
    cudaGetSymbolAddress((void**)&idx1, g_idx1);
    cudaGetSymbolAddress((void**)&idx2, g_idx2);
    cudaGetSymbolAddress((void**)&ip, g_ip);
    cudaGetSymbolAddress((void**)&qb, g_q);
    cudaGetSymbolAddress((void**)&kb, g_k);
    cudaGetSymbolAddress((void**)&vb, g_v);
    cudaGetSymbolAddress((void**)&Pb, g_P);
    cudaGetSymbolAddress((void**)&offb, g_off);
    cudaGetSymbolAddress((void**)&yf, g_yf);
    cudaGetSymbolAddress((void**)&pool, g_pool);
    cudaGetSymbolAddress((void**)&yo, g_yo);
    cudaGetSymbolAddress((void**)&st1, g_st1);
    cudaGetSymbolAddress((void**)&st2, g_st2);
    cudaGetSymbolAddress((void**)&st3, g_st3);
    cudaGetSymbolAddress((void**)&stf, g_stf);
    cudaGetSymbolAddress((void**)&sto, g_sto);
    cudaGetSymbolAddress((void**)&sb1, g_sb1);
    cudaGetSymbolAddress((void**)&sb2, g_sb2);
    cudaGetSymbolAddress((void**)&sb3, g_sb3);
    cudaGetSymbolAddress((void**)&sbf, g_sbf);
    cudaGetSymbolAddress((void**)&sbo, g_sbo);

    cudaMemsetAsync(st1, 0, sizeof(float)*2*64,  0);
    cudaMemsetAsync(st2, 0, sizeof(float)*2*128, 0);
    cudaMemsetAsync(st3, 0, sizeof(float)*2*256, 0);
    cudaMemsetAsync(stf, 0, sizeof(float)*2*256, 0);
    cudaMemsetAsync(sto, 0, sizeof(float)*2*512, 0);

    // stage 0: concat input
    k_featin<<<(BB*67*NPTS + 255)/256, 256>>>(xyz, feats, featin);

    // MLP stages (packed f32x2, double-buffered) with batch-stats BN folded forward
    k_gemm2<0,1><<<dim3(NPTS/128, 1, BB), 256>>>(W1, featin, y1, 67, 64, NPTS, nullptr, st1);
    k_fin<<<1, 64>>>(st1, g1, b1, sb1, 64, 1.f/(BB*NPTS));
    k_gemm2<1,1><<<dim3(NPTS/128, 2, BB), 256>>>(W2, y1, y2, 64, 128, NPTS, sb1, st2);
    k_fin<<<2, 64>>>(st2, g2, b2, sb2, 128, 1.f/(BB*NPTS));
    k_gemm2<1,1><<<dim3(NPTS/128, 4, BB), 256>>>(W3, y2, y3, 128, 256, NPTS, sb2, st3);
    k_fin<<<4, 64>>>(st3, g3, b3, sb3, 256, 1.f/(BB*NPTS));

    // new_features transposed to n-major (coalesced gathers)
    k_nft<<<dim3(NPTS/32, 8, BB), dim3(32, 8)>>>(y3, sb3, nft);

    // ball queries
    k_bq<<<(BB*MC*32 + 255)/256, 256>>>(xyz, ctr, idx1, NPTS);
    k_bq<<<(BB*MC*32 + 255)/256, 256>>>(ctr, ctr, idx2, MC);

    // gather ip = [group_features ; rel]
    k_ip<<<BB*16*32, 256>>>(nft, idx1, idx2, xyz, ctr, ip);

    // q, k (fused), v projections
    k_qk<<<dim3(MC*NSAMP/128, BB), 128>>>(Wq, Wk, ip, qb, kb);
    k_gemm2<0,0><<<dim3(128, 4, BB), 256>>>(Wv, ip, vb, 259, 256, MC*NSAMP, nullptr, nullptr);

    // attention: logits + softmax over n, then att_feat = V P^T fused with -gf
    k_att<<<BB*NSAMP*MC, 256>>>(qb, kb, Pb);
    k_attfeat2<<<dim3(8, 4, BB*NSAMP), 256>>>(vb, Pb, ip, offb);

    // Wf + BN stats, pool (affine+relu+residual+max over slot)
    k_gemm2<0,1><<<dim3(128, 4, BB), 256>>>(Wf, offb, yf, 256, 256, MC*NSAMP, nullptr, stf);
    k_fin<<<4, 64>>>(stf, gp, bp, sbf, 256, 1.f/(BB*MC*NSAMP));
    k_pool<<<(BB*256*MC + 255)/256, 256>>>(yf, sbf, ip, pool);

    // output conv + BN
    k_gemm2<0,1><<<dim3(MC/128, 8, BB), 256>>>(Wo, pool, yo, 256, 512, MC, nullptr, sto);
    k_fin<<<8, 64>>>(sto, go, bo, sbo, 512, 1.f/(BB*MC));

    int has_ctr = (out_size == BB*MC*3 + BB*512*MC) ? 1 : 0;
    int total = (has_ctr ? BB*MC*3 : 0) + BB*512*MC;
    k_final<<<(total + 255)/256, 256>>>(yo, sbo, ctr, outp, has_ctr);
}

// round 6
// speedup vs baseline: 1.9972x; 1.8824x over previous
#include <cuda_runtime.h>
#include <cstdint>

// ---------------- problem constants ----------------
#define BB    4
#define NPTS  8192
#define MC    1024
#define NSAMP 16
#define CFEAT 64
#define RAD2  0.25f
#define EPSBN 1e-5f

#define FMA2(acc, a, b) asm("fma.rn.f32x2 %0, %1, %2, %0;" : "+l"(acc) : "l"(a), "l"(b))

// ---------------- mma.sync tf32 helpers (arch-agnostic PTX, works on sm_103) --------
__device__ __forceinline__ float to_tf32(float x) {
    uint32_t r;
    asm("cvt.rna.tf32.f32 %0, %1;" : "=r"(r) : "f"(x));
    return __uint_as_float(r);
}
__device__ __forceinline__ void mma8(float* d, const uint32_t* a, const uint32_t* b) {
    asm volatile(
        "mma.sync.aligned.m16n8k8.row.col.f32.tf32.tf32.f32 "
        "{%0,%1,%2,%3}, {%4,%5,%6,%7}, {%8,%9}, {%0,%1,%2,%3};"
        : "+f"(d[0]), "+f"(d[1]), "+f"(d[2]), "+f"(d[3])
        : "r"(a[0]), "r"(a[1]), "r"(a[2]), "r"(a[3]), "r"(b[0]), "r"(b[1]));
}

// smem tile: 128 rows x 32 k floats, padded stride 36
#define TSTR   36
#define TILEF  (128*TSTR)            // floats per tile
#define MMA_SMEM_BYTES (2*2*TILEF*4) // 73728

// ---------------- scratch (__device__ globals; no runtime alloc) ----------------
static __device__ float g_featin[(size_t)BB*67*NPTS];
static __device__ float g_y1[(size_t)BB*64*NPTS];
static __device__ float g_y2[(size_t)BB*128*NPTS];
static __device__ float g_y3[(size_t)BB*256*NPTS];
static __device__ float g_nft[(size_t)BB*NPTS*256];
static __device__ int   g_idx1[BB*MC*NSAMP];
static __device__ int   g_idx2[BB*MC*NSAMP];
static __device__ float g_ip[(size_t)BB*259*MC*NSAMP];
static __device__ float g_q[(size_t)BB*8*MC*NSAMP];
static __device__ float g_k[(size_t)BB*8*MC*NSAMP];
static __device__ float g_v[(size_t)BB*256*MC*NSAMP];
static __device__ float g_P[(size_t)BB*NSAMP*MC*MC];
static __device__ float g_off[(size_t)BB*256*MC*NSAMP];
static __device__ float g_yf[(size_t)BB*256*MC*NSAMP];
static __device__ float g_pool[(size_t)BB*256*MC];
static __device__ float g_yo[(size_t)BB*512*MC];
static __device__ float g_st1[2*64], g_st2[2*128], g_st3[2*256], g_stf[2*256], g_sto[2*512];
static __device__ float g_sb1[2*64], g_sb2[2*128], g_sb3[2*256], g_sbf[2*256], g_sbo[2*512];

// ---------------- build concat(xyz^T, features) ----------------
__global__ void k_featin(const float* __restrict__ xyz, const float* __restrict__ feats,
                         float* __restrict__ out)
{
    int i = blockIdx.x * 256 + threadIdx.x;
    if (i >= BB*67*NPTS) return;
    int n  = i % NPTS;
    int ch = (i / NPTS) % 67;
    int b  = i / (NPTS*67);
    float v;
    if (ch < 3) v = xyz[((size_t)b*NPTS + n)*3 + ch];
    else        v = feats[((size_t)b*CFEAT + (ch-3))*NPTS + n];
    out[i] = v;
}

// ======== FFMA2 GEMM (MLP stages + Wo) ========
template<int MODE, int STATS>
__global__ void __launch_bounds__(256, 2)
k_gemm2(const float* __restrict__ W, const float* __restrict__ X,
        float* __restrict__ Y, int Cin, int Cout, int NCOL,
        const float* __restrict__ sb, float* __restrict__ stats)
{
    const int b = blockIdx.z;
    const float* Xb = X + (size_t)b * Cin * NCOL;
    float* Yb = Y + (size_t)b * Cout * NCOL;
    const int col0 = blockIdx.x * 128;
    const int row0 = blockIdx.y * 64;
    __shared__ float Wd[2][16][132];
    __shared__ float Xs[2][16][132];
    const int tid = threadIdx.x;
    const int tx = tid & 15, ty = tid >> 4;
    const int wkk = tid & 15, wrb = tid >> 4;
    const int xcol = tid & 127, xkb = tid >> 7;
    float wreg[4];
    float xreg[8];
    const int nch = (Cin + 15) >> 4;

    {
#pragma unroll
        for (int p = 0; p < 4; p++) {
            float w = 0.f;
            if (wkk < Cin) w = W[(size_t)(row0 + wrb + 16*p)*Cin + wkk];
            wreg[p] = w;
        }
#pragma unroll
        for (int t = 0; t < 8; t++) {
            int cg = xkb + 2*t;
            float v = 0.f;
            if (cg < Cin) {
                v = Xb[(size_t)cg*NCOL + col0 + xcol];
                if (MODE == 1) v = fmaxf(fmaf(v, sb[cg], sb[Cin+cg]), 0.f);
            }
            xreg[t] = v;
        }
    }
#pragma unroll
    for (int p = 0; p < 4; p++) *(float2*)&Wd[0][wkk][2*(wrb+16*p)] = make_float2(wreg[p], wreg[p]);
#pragma unroll
    for (int t = 0; t < 8; t++) Xs[0][xkb + 2*t][xcol] = xreg[t];
    __syncthreads();

    unsigned long long acc[4][4];
#pragma unroll
    for (int i = 0; i < 4; i++)
#pragma unroll
        for (int p = 0; p < 4; p++) acc[i][p] = 0ull;

    for (int c = 0; c < nch; c++) {
        int buf = c & 1;
        if (c + 1 < nch) {
            int k0 = (c + 1) << 4;
#pragma unroll
            for (int p = 0; p < 4; p++) {
                float w = 0.f;
                if (k0 + wkk < Cin) w = W[(size_t)(row0 + wrb + 16*p)*Cin + k0 + wkk];
                wreg[p] = w;
            }
#pragma unroll
            for (int t = 0; t < 8; t++) {
                int cg = k0 + xkb + 2*t;
                float v = 0.f;
                if (cg < Cin) {
                    v = Xb[(size_t)cg*NCOL + col0 + xcol];
                    if (MODE == 1) v = fmaxf(fmaf(v, sb[cg], sb[Cin+cg]), 0.f);
                }
                xreg[t] = v;
            }
        }
#pragma unroll
        for (int kk = 0; kk < 16; kk++) {
            ulonglong2 wa = *(const ulonglong2*)&Wd[buf][kk][ty*8];
            ulonglong2 wb = *(const ulonglong2*)&Wd[buf][kk][ty*8 + 4];
            ulonglong2 xa = *(const ulonglong2*)&Xs[buf][kk][tx*4];
            ulonglong2 xb = *(const ulonglong2*)&Xs[buf][kk][64 + tx*4];
            unsigned long long wp[4] = {wa.x, wa.y, wb.x, wb.y};
            unsigned long long xp[4] = {xa.x, xa.y, xb.x, xb.y};
#pragma unroll
            for (int i = 0; i < 4; i++) {
                FMA2(acc[i][0], wp[i], xp[0]);
                FMA2(acc[i][1], wp[i], xp[1]);
                FMA2(acc[i][2], wp[i], xp[2]);
                FMA2(acc[i][3], wp[i], xp[3]);
            }
        }
        if (c + 1 < nch) {
            int nb = buf ^ 1;
#pragma unroll
            for (int p = 0; p < 4; p++) *(float2*)&Wd[nb][wkk][2*(wrb+16*p)] = make_float2(wreg[p], wreg[p]);
#pragma unroll
            for (int t = 0; t < 8; t++) Xs[nb][xkb + 2*t][xcol] = xreg[t];
            __syncthreads();
        }
    }

#pragma unroll
    for (int i = 0; i < 4; i++) {
        int r = row0 + ty*4 + i;
        float rs = 0.f, rq = 0.f;
        float v[8];
#pragma unroll
        for (int p = 0; p < 4; p++) {
            float lo, hi;
            asm("mov.b64 {%0, %1}, %2;" : "=f"(lo), "=f"(hi) : "l"(acc[i][p]));
            v[p*2] = lo; v[p*2+1] = hi;
            rs += lo + hi; rq += lo*lo + hi*hi;
        }
        *(float4*)&Yb[(size_t)r*NCOL + col0 + tx*4]      = make_float4(v[0], v[1], v[2], v[3]);
        *(float4*)&Yb[(size_t)r*NCOL + col0 + 64 + tx*4] = make_float4(v[4], v[5], v[6], v[7]);
        if (STATS) {
#pragma unroll
            for (int o = 8; o > 0; o >>= 1) {
                rs += __shfl_down_sync(0xffffffffu, rs, o);
                rq += __shfl_down_sync(0xffffffffu, rq, o);
            }
            if (tx == 0) { atomicAdd(&stats[r], rs); atomicAdd(&stats[Cout + r], rq); }
        }
    }
}

// ======== mma.sync tf32 core: acc += A_tile(128x32) * B_tile(128x32)^T ========
// As/Bs: [128][36] floats, k-contiguous rows. Warp grid 4(m) x 2(n).
__device__ __forceinline__ void mma_tile(const float* As, const float* Bs,
                                         float acc[2][8][4], int warp_m, int warp_n,
                                         int g, int t4)
{
#pragma unroll
    for (int ks = 0; ks < 4; ks++) {
        const int kb = ks * 8;
        uint32_t a[2][4];
#pragma unroll
        for (int fm = 0; fm < 2; fm++) {
            const int rm = warp_m*32 + fm*16;
            a[fm][0] = __float_as_uint(As[(rm + g)*TSTR + kb + t4]);
            a[fm][1] = __float_as_uint(As[(rm + 8 + g)*TSTR + kb + t4]);
            a[fm][2] = __float_as_uint(As[(rm + g)*TSTR + kb + 4 + t4]);
            a[fm][3] = __float_as_uint(As[(rm + 8 + g)*TSTR + kb + 4 + t4]);
        }
#pragma unroll
        for (int fn = 0; fn < 8; fn++) {
            const int rn = warp_n*64 + fn*8;
            uint32_t b[2];
            b[0] = __float_as_uint(Bs[(rn + g)*TSTR + kb + t4]);
            b[1] = __float_as_uint(Bs[(rn + g)*TSTR + kb + 4 + t4]);
            mma8(acc[0][fn], a[0], b);
            mma8(acc[1][fn], a[1], b);
        }
    }
}

// ======== attfeat (NT): off[c,j] = sum_n V[c,n] P[j,n] - gf[c,j] ========
__global__ void __launch_bounds__(256, 2)
k_mma_nt(const float* __restrict__ V, const float* __restrict__ P,
         const float* __restrict__ ip, float* __restrict__ off)
{
    extern __shared__ float sm[];
    const int tid = threadIdx.x, wid = tid >> 5, lane = tid & 31;
    const int warp_m = wid >> 1, warp_n = wid & 1;
    const int g = lane >> 2, t4 = lane & 3;
    const int bs = blockIdx.z, slot = bs & 15, b = bs >> 4;
    const float* Vb = V + ((size_t)b*256*NSAMP + slot)*MC;
    const float* Pb = P + ((size_t)(b*NSAMP + slot))*MC*MC;
    const int j0 = blockIdx.x * 128;
    const int c0 = blockIdx.y * 128;

    const int arow = tid >> 3, afo = tid & 7;   // 4 f4/thread: rows arow + 32*it? no: idx scheme below

    float acc[2][8][4];
#pragma unroll
    for (int i = 0; i < 2; i++)
#pragma unroll
        for (int j = 0; j < 8; j++)
#pragma unroll
            for (int p = 0; p < 4; p++) acc[i][j][p] = 0.f;

    float4 pa[4], pb[4];
    // prefetch chunk 0
#pragma unroll
    for (int it = 0; it < 4; it++) {
        int idx = tid + 256*it, row = idx >> 3, f = idx & 7;
        pa[it] = *(const float4*)&Vb[(size_t)(c0+row)*(NSAMP*MC) + 4*f];
        pb[it] = *(const float4*)&Pb[(size_t)(j0+row)*MC + 4*f];
    }
    {
        float* As = sm; float* Bs = sm + TILEF;
#pragma unroll
        for (int it = 0; it < 4; it++) {
            int idx = tid + 256*it, row = idx >> 3, f = idx & 7;
            *(float4*)&As[row*TSTR + 4*f] = make_float4(to_tf32(pa[it].x), to_tf32(pa[it].y),
                                                        to_tf32(pa[it].z), to_tf32(pa[it].w));
            *(float4*)&Bs[row*TSTR + 4*f] = make_float4(to_tf32(pb[it].x), to_tf32(pb[it].y),
                                                        to_tf32(pb[it].z), to_tf32(pb[it].w));
        }
    }
    __syncthreads();

    const int nch = MC / 32;
    for (int c = 0; c < nch; c++) {
        const int buf = c & 1;
        if (c + 1 < nch) {
            const int n0 = (c + 1) * 32;
#pragma unroll
            for (int it = 0; it < 4; it++) {
                int idx = tid + 256*it, row = idx >> 3, f = idx & 7;
                pa[it] = *(const float4*)&Vb[(size_t)(c0+row)*(NSAMP*MC) + n0 + 4*f];
                pb[it] = *(const float4*)&Pb[(size_t)(j0+row)*MC + n0 + 4*f];
            }
        }
        mma_tile(sm + buf*2*TILEF, sm + buf*2*TILEF + TILEF, acc, warp_m, warp_n, g, t4);
        if (c + 1 < nch) {
            const int nb = buf ^ 1;
            float* As = sm + nb*2*TILEF; float* Bs = As + TILEF;
            __syncthreads();
#pragma unroll
            for (int it = 0; it < 4; it++) {
                int idx = tid + 256*it, row = idx >> 3, f = idx & 7;
                *(float4*)&As[row*TSTR + 4*f] = make_float4(to_tf32(pa[it].x), to_tf32(pa[it].y),
                                                            to_tf32(pa[it].z), to_tf32(pa[it].w));
                *(float4*)&Bs[row*TSTR + 4*f] = make_float4(to_tf32(pb[it].x), to_tf32(pb[it].y),
                                                            to_tf32(pb[it].z), to_tf32(pb[it].w));
            }
            __syncthreads();
        }
    }

    // epilogue: subtract group_features, write off
#pragma unroll
    for (int fm = 0; fm < 2; fm++) {
        const int r0 = c0 + warp_m*32 + fm*16 + g;
        const int r1 = r0 + 8;
        const float* ip0 = ip + (((size_t)b*259 + r0)*NSAMP + slot)*MC;
        const float* ip1 = ip + (((size_t)b*259 + r1)*NSAMP + slot)*MC;
        float* of0 = off + (((size_t)b*256 + r0)*NSAMP + slot)*MC;
        float* of1 = off + (((size_t)b*256 + r1)*NSAMP + slot)*MC;
#pragma unroll
        for (int fn = 0; fn < 8; fn++) {
            const int jj = j0 + warp_n*64 + fn*8 + 2*t4;
            float2 ga = *(const float2*)&ip0[jj];
            float2 gb = *(const float2*)&ip1[jj];
            *(float2*)&of0[jj] = make_float2(acc[fm][fn][0] - ga.x, acc[fm][fn][1] - ga.y);
            *(float2*)&of1[jj] = make_float2(acc[fm][fn][2] - gb.x, acc[fm][fn][3] - gb.y);
        }
    }
}

// ======== NN: Y[b,o,col] = sum_k W[o,k] X[b,k,col] (tf32 mma) ========
template<int STATS>
__global__ void __launch_bounds__(256, 2)
k_mma_nn(const float* __restrict__ W, const float* __restrict__ X,
         float* __restrict__ Y, int Cin, int Cout, float* __restrict__ stats)
{
    extern __shared__ float sm[];
    const int tid = threadIdx.x, wid = tid >> 5, lane = tid & 31;
    const int warp_m = wid >> 1, warp_n = wid & 1;
    const int g = lane >> 2, t4 = lane & 3;
    const int b = blockIdx.z;
    const int NCOL = MC * NSAMP;
    const float* Xb = X + (size_t)b * Cin * NCOL;
    const int ncol0 = blockIdx.x * 128;
    const int row0 = blockIdx.y * 128;
    const bool al4 = (Cin & 3) == 0;

    float acc[2][8][4];
#pragma unroll
    for (int i = 0; i < 2; i++)
#pragma unroll
        for (int j = 0; j < 8; j++)
#pragma unroll
            for (int p = 0; p < 4; p++) acc[i][j][p] = 0.f;

    float4 pa[4], pb[4];
    const int nch = (Cin + 31) >> 5;

    // loaders
    auto loadA = [&](int k0, float4* dst) {
#pragma unroll
        for (int it = 0; it < 4; it++) {
            int idx = tid + 256*it, row = idx >> 3, f = idx & 7;
            int k = k0 + 4*f;
            const float* wr = &W[(size_t)(row0+row)*Cin];
            float4 w4;
            if (al4 && k + 3 < Cin) w4 = *(const float4*)&wr[k];
            else {
                w4.x = (k+0 < Cin) ? wr[k+0] : 0.f;
                w4.y = (k+1 < Cin) ? wr[k+1] : 0.f;
                w4.z = (k+2 < Cin) ? wr[k+2] : 0.f;
                w4.w = (k+3 < Cin) ? wr[k+3] : 0.f;
            }
            dst[it] = w4;
        }
    };
    auto loadB = [&](int k0, float4* dst) {
#pragma unroll
        for (int it = 0; it < 4; it++) {
            int kk = k0 + lane;             // lane-distinct k rows
            int n4 = (tid >> 5) + 8*it;     // warp-distinct n quads
            float4 x4 = make_float4(0.f, 0.f, 0.f, 0.f);
            if (kk < Cin) x4 = *(const float4*)&Xb[(size_t)kk*NCOL + ncol0 + 4*n4];
            dst[it] = x4;
        }
    };
    auto storeT = [&](int bufbase, const float4* va, const float4* vb) {
        float* As = sm + bufbase; float* Bs = As + TILEF;
#pragma unroll
        for (int it = 0; it < 4; it++) {
            int idx = tid + 256*it, row = idx >> 3, f = idx & 7;
            *(float4*)&As[row*TSTR + 4*f] = make_float4(to_tf32(va[it].x), to_tf32(va[it].y),
                                                        to_tf32(va[it].z), to_tf32(va[it].w));
            int kk = lane;
            int n4 = (tid >> 5) + 8*it;
            Bs[(4*n4 + 0)*TSTR + kk] = to_tf32(vb[it].x);
            Bs[(4*n4 + 1)*TSTR + kk] = to_tf32(vb[it].y);
            Bs[(4*n4 + 2)*TSTR + kk] = to_tf32(vb[it].z);
            Bs[(4*n4 + 3)*TSTR + kk] = to_tf32(vb[it].w);
        }
    };

    loadA(0, pa); loadB(0, pb);
    storeT(0, pa, pb);
    __syncthreads();

    for (int c = 0; c < nch; c++) {
        const int buf = c & 1;
        if (c + 1 < nch) { loadA((c+1)*32, pa); loadB((c+1)*32, pb); }
        mma_tile(sm + buf*2*TILEF, sm + buf*2*TILEF + TILEF, acc, warp_m, warp_n, g, t4);
        if (c + 1 < nch) {
            __syncthreads();
            storeT((buf^1)*2*TILEF, pa, pb);
            __syncthreads();
        }
    }

    // epilogue
#pragma unroll
    for (int fm = 0; fm < 2; fm++) {
        const int r0 = row0 + warp_m*32 + fm*16 + g;
        const int r1 = r0 + 8;
        float* y0 = Y + ((size_t)b*Cout + r0)*NCOL + ncol0;
        float* y1 = Y + ((size_t)b*Cout + r1)*NCOL + ncol0;
        float s0 = 0.f, q0 = 0.f, s1 = 0.f, q1 = 0.f;
#pragma unroll
        for (int fn = 0; fn < 8; fn++) {
            const int jj = warp_n*64 + fn*8 + 2*t4;
            float d0 = acc[fm][fn][0], d1 = acc[fm][fn][1];
            float d2 = acc[fm][fn][2], d3 = acc[fm][fn][3];
            *(float2*)&y0[jj] = make_float2(d0, d1);
            *(float2*)&y1[jj] = make_float2(d2, d3);
            if (STATS) {
                s0 += d0 + d1; q0 += d0*d0 + d1*d1;
                s1 += d2 + d3; q1 += d2*d2 + d3*d3;
            }
        }
        if (STATS) {
#pragma unroll
            for (int o = 1; o < 4; o <<= 1) {
                s0 += __shfl_xor_sync(0xffffffffu, s0, o);
                q0 += __shfl_xor_sync(0xffffffffu, q0, o);
                s1 += __shfl_xor_sync(0xffffffffu, s1, o);
                q1 += __shfl_xor_sync(0xffffffffu, q1, o);
            }
            if (t4 == 0) {
                atomicAdd(&stats[r0], s0); atomicAdd(&stats[Cout + r0], q0);
                atomicAdd(&stats[r1], s1); atomicAdd(&stats[Cout + r1], q1);
            }
        }
    }
}

// ---------------- fused q+k projection ----------------
__global__ void k_qk(const float* __restrict__ Wq, const float* __restrict__ Wk,
                     const float* __restrict__ X, float* __restrict__ q,
                     float* __restrict__ k)
{
    const int b = blockIdx.y;
    const int NCOL = MC*NSAMP;
    const float* Xb = X + (size_t)b * 259 * NCOL;
    __shared__ float Ws[16][260];
    for (int i = threadIdx.x; i < 8*259; i += 128) {
        int r = i / 259, c = i % 259;
        Ws[r][c] = Wq[i];
        Ws[r+8][c] = Wk[i];
    }
    __syncthreads();
    int col = blockIdx.x * 128 + threadIdx.x;
    float acc[16];
#pragma unroll
    for (int o = 0; o < 16; o++) acc[o] = 0.f;
    for (int c = 0; c < 259; c++) {
        float xv = Xb[(size_t)c*NCOL + col];
#pragma unroll
        for (int o = 0; o < 16; o++) acc[o] = fmaf(Ws[o][c], xv, acc[o]);
    }
#pragma unroll
    for (int o = 0; o < 8; o++) {
        q[((size_t)b*8 + o)*NCOL + col] = acc[o];
        k[((size_t)b*8 + o)*NCOL + col] = acc[o+8];
    }
}

// ---------------- BN finalize ----------------
__global__ void k_fin(const float* __restrict__ stats, const float* __restrict__ g,
                      const float* __restrict__ be, float* __restrict__ sb,
                      int Cc, float invcnt)
{
    int c = blockIdx.x * 64 + threadIdx.x;
    if (c >= Cc) return;
    float mu  = stats[c] * invcnt;
    float var = stats[Cc + c] * invcnt - mu*mu;
    float s = g[c] * rsqrtf(var + EPSBN);
    sb[c] = s;
    sb[Cc + c] = be[c] - mu * s;
}

// ---------------- ball query ----------------
__global__ void k_bq(const float* __restrict__ src, const float* __restrict__ ctr,
                     int* __restrict__ out, int NSRC)
{
    int gw = (blockIdx.x * blockDim.x + threadIdx.x) >> 5;
    int lane = threadIdx.x & 31;
    __shared__ int lists[8][NSAMP];
    int* list = lists[threadIdx.x >> 5];
    if (gw >= BB*MC) return;
    int b = gw / MC, m = gw % MC;
    float cx = ctr[((size_t)b*MC + m)*3 + 0];
    float cy = ctr[((size_t)b*MC + m)*3 + 1];
    float cz = ctr[((size_t)b*MC + m)*3 + 2];
    int count = 0;
    for (int base = 0; base < NSRC; base += 32) {
        int n = base + lane;
        bool ok = false;
        if (n < NSRC) {
            float dx = src[((size_t)b*NSRC + n)*3 + 0] - cx;
            float dy = src[((size_t)b*NSRC + n)*3 + 1] - cy;
            float dz = src[((size_t)b*NSRC + n)*3 + 2] - cz;
            ok = (dx*dx + dy*dy + dz*dz) < RAD2;
        }
        unsigned mk = __ballot_sync(0xffffffffu, ok);
        if (ok) {
            int pos = count + __popc(mk & ((1u << lane) - 1u));
            if (pos < NSAMP) list[pos] = n;
        }
        count += __popc(mk);
        if (count >= NSAMP) break;
    }
    __syncwarp();
    if (lane < NSAMP) {
        int v;
        if (count == 0) v = 0;
        else v = (lane < count) ? list[lane] : list[0];
        out[((size_t)b*MC + m)*NSAMP + lane] = v;
    }
}

// ---------------- new_features transpose with affine+relu ----------------
__global__ void k_nft(const float* __restrict__ y3, const float* __restrict__ sb3,
                      float* __restrict__ nft)
{
    int b = blockIdx.z;
    int n0 = blockIdx.x * 32, c0 = blockIdx.y * 32;
    __shared__ float t[32][33];
#pragma unroll
    for (int i = 0; i < 4; i++) {
        int c = c0 + threadIdx.y + i*8;
        int n = n0 + threadIdx.x;
        float v = y3[((size_t)b*256 + c)*NPTS + n];
        v = fmaxf(fmaf(v, sb3[c], sb3[256 + c]), 0.f);
        t[threadIdx.y + i*8][threadIdx.x] = v;
    }
    __syncthreads();
#pragma unroll
    for (int i = 0; i < 4; i++) {
        int n = n0 + threadIdx.y + i*8;
        int c = c0 + threadIdx.x;
        nft[((size_t)b*NPTS + n)*256 + c] = t[threadIdx.x][threadIdx.y + i*8];
    }
}

// ---------------- build ip ----------------
__global__ void k_ip(const float* __restrict__ nft, const int* __restrict__ idx1,
                     const int* __restrict__ idx2, const float* __restrict__ xyz,
                     const float* __restrict__ ctr, float* __restrict__ ip)
{
    int bz = blockIdx.x;
    int cblk = bz & 31;
    int slot = (bz >> 5) & 15;
    int b    = bz >> 9;
    __shared__ float s[256][33];
    int warp = threadIdx.x >> 5, lane = threadIdx.x & 31;
#pragma unroll
    for (int w = 0; w < 4; w++) {
        int center = cblk*32 + warp*4 + w;
        int id = idx1[((size_t)b*MC + center)*NSAMP + slot];
        const float* srcp = nft + ((size_t)b*NPTS + id)*256;
#pragma unroll
        for (int t = 0; t < 8; t++) s[lane + t*32][warp*4 + w] = srcp[lane + t*32];
    }
    __syncthreads();
    int center = threadIdx.x & 31, chb = threadIdx.x >> 5;
#pragma unroll
    for (int t = 0; t < 32; t++) {
        int ch = chb + t*8;
        ip[(((size_t)b*259 + ch)*NSAMP + slot)*MC + cblk*32 + center] = s[ch][center];
    }
    if (threadIdx.x < 96) {
        int d = threadIdx.x / 32;
        int cc = threadIdx.x & 31;
        int ctr_i = cblk*32 + cc;
        int i1 = idx1[((size_t)b*MC + ctr_i)*NSAMP + slot];
        int i2 = idx2[((size_t)b*MC + ctr_i)*NSAMP + slot];
        float r = ctr[((size_t)b*MC + i2)*3 + d] - xyz[((size_t)b*NPTS + i1)*3 + d];
        ip[(((size_t)b*259 + 256 + d)*NSAMP + slot)*MC + ctr_i] = r;
    }
}

// ---------------- attention logits + column softmax ----------------
__global__ void k_att(const float* __restrict__ q, const float* __restrict__ k,
                      float* __restrict__ P)
{
    int bx = blockIdx.x;
    int j = bx & (MC-1);
    int slot = (bx >> 10) & 15;
    int b = bx >> 14;
    __shared__ float red[256];
    float qv[8];
#pragma unroll
    for (int c = 0; c < 8; c++)
        qv[c] = q[(((size_t)b*8 + c)*NSAMP + slot)*MC + j];
    const float* kb = k + ((size_t)b*8*NSAMP + slot)*MC;
    float s[4];
#pragma unroll
    for (int t = 0; t < 4; t++) {
        int n = threadIdx.x + t*256;
        float a = 0.f;
#pragma unroll
        for (int c = 0; c < 8; c++) a = fmaf(kb[(size_t)c*NSAMP*MC + n], qv[c], a);
        s[t] = a;
    }
    float mx = fmaxf(fmaxf(s[0], s[1]), fmaxf(s[2], s[3]));
    red[threadIdx.x] = mx; __syncthreads();
    for (int o = 128; o > 0; o >>= 1) {
        if (threadIdx.x < o) red[threadIdx.x] = fmaxf(red[threadIdx.x], red[threadIdx.x + o]);
        __syncthreads();
    }
    mx = red[0]; __syncthreads();
    float es[4]; float sum = 0.f;
#pragma unroll
    for (int t = 0; t < 4; t++) { es[t] = __expf(s[t] - mx); sum += es[t]; }
    red[threadIdx.x] = sum; __syncthreads();
    for (int o = 128; o > 0; o >>= 1) {
        if (threadIdx.x < o) red[threadIdx.x] += red[threadIdx.x + o];
        __syncthreads();
    }
    float inv = 1.f / red[0];
    float* Pb = P + (((size_t)(b*NSAMP + slot))*MC + j)*MC;
#pragma unroll
    for (int t = 0; t < 4; t++) Pb[threadIdx.x + t*256] = es[t] * inv;
}

// ---------------- relu(affine(yf)) + gf residual, max-pool over slot ----------------
__global__ void k_pool(const float* __restrict__ yf, const float* __restrict__ sbf,
                       const float* __restrict__ ip, float* __restrict__ pool)
{
    int i = blockIdx.x * 256 + threadIdx.x;
    if (i >= BB*256*MC) return;
    int center = i & (MC-1);
    int c = (i >> 10) & 255;
    int b = i >> 18;
    float s = sbf[c], bi = sbf[256 + c];
    float mx = -1e30f;
#pragma unroll
    for (int slot = 0; slot < NSAMP; slot++) {
        float v = fmaxf(fmaf(yf[(((size_t)b*256 + c)*NSAMP + slot)*MC + center], s, bi), 0.f);
        v += ip[(((size_t)b*259 + c)*NSAMP + slot)*MC + center];
        mx = fmaxf(mx, v);
    }
    pool[((size_t)b*256 + c)*MC + center] = mx;
}

// ---------------- final ----------------
__global__ void k_final(const float* __restrict__ yo, const float* __restrict__ sbo,
                        const float* __restrict__ ctr, float* __restrict__ out, int has_ctr)
{
    int off0 = has_ctr ? BB*MC*3 : 0;
    int total = off0 + BB*512*MC;
    int i = blockIdx.x * 256 + threadIdx.x;
    if (i >= total) return;
    if (i < off0) { out[i] = ctr[i]; return; }
    int j = i - off0;
    int ch = (j >> 10) & 511;
    out[i] = fmaxf(fmaf(yo[j], sbo[ch], sbo[512 + ch]), 0.f);
}

// ---------------- host launch ----------------
extern "C" void kernel_launch(void* const* d_in, const int* in_sizes, int n_in,
                              void* d_out, int out_size)
{
    const float* xyz   = (const float*)d_in[0];
    const float* feats = (const float*)d_in[1];
    const float* ctr   = (const float*)d_in[2];
    const float* W1 = (const float*)d_in[3];
    const float* g1 = (const float*)d_in[4];
    const float* b1 = (const float*)d_in[5];
    const float* W2 = (const float*)d_in[6];
    const float* g2 = (const float*)d_in[7];
    const float* b2 = (const float*)d_in[8];
    const float* W3 = (const float*)d_in[9];
    const float* g3 = (const float*)d_in[10];
    const float* b3 = (const float*)d_in[11];
    const float* Wq = (const float*)d_in[12];
    const float* Wk = (const float*)d_in[13];
    const float* Wv = (const float*)d_in[14];
    const float* Wf = (const float*)d_in[15];
    const float* gp = (const float*)d_in[16];
    const float* bp = (const float*)d_in[17];
    const float* Wo = (const float*)d_in[18];
    const float* go = (const float*)d_in[19];
    const float* bo = (const float*)d_in[20];
    float* outp = (float*)d_out;

    float *featin, *y1, *y2, *y3, *nft, *ip, *qb, *kb, *vb, *Pb, *offb, *yf, *pool, *yo;
    int *idx1, *idx2;
    float *st1, *st2, *st3, *stf, *sto, *sb1, *sb2, *sb3, *sbf, *sbo;
    cudaGetSymbolAddress((void**)&featin, g_featin);
    cudaGetSymbolAddress((void**)&y1, g_y1);
    cudaGetSymbolAddress((void**)&y2, g_y2);
    cudaGetSymbolAddress((void**)&y3, g_y3);
    cudaGetSymbolAddress((void**)&nft, g_nft);
    cudaGetSymbolAddress((void**)&idx1, g_idx1);
    cudaGetSymbolAddress((void**)&idx2, g_idx2);
    cudaGetSymbolAddress((void**)&ip, g_ip);
    cudaGetSymbolAddress((void**)&qb, g_q);
    cudaGetSymbolAddress((void**)&kb, g_k);
    cudaGetSymbolAddress((void**)&vb, g_v);
    cudaGetSymbolAddress((void**)&Pb, g_P);
    cudaGetSymbolAddress((void**)&offb, g_off);
    cudaGetSymbolAddress((void**)&yf, g_yf);
    cudaGetSymbolAddress((void**)&pool, g_pool);
    cudaGetSymbolAddress((void**)&yo, g_yo);
    cudaGetSymbolAddress((void**)&st1, g_st1);
    cudaGetSymbolAddress((void**)&st2, g_st2);
    cudaGetSymbolAddress((void**)&st3, g_st3);
    cudaGetSymbolAddress((void**)&stf, g_stf);
    cudaGetSymbolAddress((void**)&sto, g_sto);
    cudaGetSymbolAddress((void**)&sb1, g_sb1);
    cudaGetSymbolAddress((void**)&sb2, g_sb2);
    cudaGetSymbolAddress((void**)&sb3, g_sb3);
    cudaGetSymbolAddress((void**)&sbf, g_sbf);
    cudaGetSymbolAddress((void**)&sbo, g_sbo);

    cudaFuncSetAttribute(k_mma_nt, cudaFuncAttributeMaxDynamicSharedMemorySize, MMA_SMEM_BYTES);
    cudaFuncSetAttribute(k_mma_nn<0>, cudaFuncAttributeMaxDynamicSharedMemorySize, MMA_SMEM_BYTES);
    cudaFuncSetAttribute(k_mma_nn<1>, cudaFuncAttributeMaxDynamicSharedMemorySize, MMA_SMEM_BYTES);

    cudaMemsetAsync(st1, 0, sizeof(float)*2*64,  0);
    cudaMemsetAsync(st2, 0, sizeof(float)*2*128, 0);
    cudaMemsetAsync(st3, 0, sizeof(float)*2*256, 0);
    cudaMemsetAsync(stf, 0, sizeof(float)*2*256, 0);
    cudaMemsetAsync(sto, 0, sizeof(float)*2*512, 0);

    k_featin<<<(BB*67*NPTS + 255)/256, 256>>>(xyz, feats, featin);

    // MLP (FFMA2)
    k_gemm2<0,1><<<dim3(NPTS/128, 1, BB), 256>>>(W1, featin, y1, 67, 64, NPTS, nullptr, st1);
    k_fin<<<1, 64>>>(st1, g1, b1, sb1, 64, 1.f/(BB*NPTS));
    k_gemm2<1,1><<<dim3(NPTS/128, 2, BB), 256>>>(W2, y1, y2, 64, 128, NPTS, sb1, st2);
    k_fin<<<2, 64>>>(st2, g2, b2, sb2, 128, 1.f/(BB*NPTS));
    k_gemm2<1,1><<<dim3(NPTS/128, 4, BB), 256>>>(W3, y2, y3, 128, 256, NPTS, sb2, st3);
    k_fin<<<4, 64>>>(st3, g3, b3, sb3, 256, 1.f/(BB*NPTS));

    k_nft<<<dim3(NPTS/32, 8, BB), dim3(32, 8)>>>(y3, sb3, nft);

    k_bq<<<(BB*MC*32 + 255)/256, 256>>>(xyz, ctr, idx1, NPTS);
    k_bq<<<(BB*MC*32 + 255)/256, 256>>>(ctr, ctr, idx2, MC);

    k_ip<<<BB*16*32, 256>>>(nft, idx1, idx2, xyz, ctr, ip);

    // q, k (fused FFMA), v (tf32 mma)
    k_qk<<<dim3(MC*NSAMP/128, BB), 128>>>(Wq, Wk, ip, qb, kb);
    k_mma_nn<0><<<dim3(128, 2, BB), 256, MMA_SMEM_BYTES>>>(Wv, ip, vb, 259, 256, nullptr);

    // attention
    k_att<<<BB*NSAMP*MC, 256>>>(qb, kb, Pb);
    k_mma_nt<<<dim3(8, 2, BB*NSAMP), 256, MMA_SMEM_BYTES>>>(vb, Pb, ip, offb);

    // Wf (tf32 mma + BN stats), pool
    k_mma_nn<1><<<dim3(128, 2, BB), 256, MMA_SMEM_BYTES>>>(Wf, offb, yf, 256, 256, stf);
    k_fin<<<4, 64>>>(stf, gp, bp, sbf, 256, 1.f/(BB*MC*NSAMP));
    k_pool<<<(BB*256*MC + 255)/256, 256>>>(yf, sbf, ip, pool);

    // output conv (FFMA2)
    k_gemm2<0,1><<<dim3(MC/128, 8, BB), 256>>>(Wo, pool, yo, 256, 512, MC, nullptr, sto);
    k_fin<<<8, 64>>>(sto, go, bo, sbo, 512, 1.f/(BB*MC));

    int has_ctr = (out_size == BB*MC*3 + BB*512*MC) ? 1 : 0;
    int total = (has_ctr ? BB*MC*3 : 0) + BB*512*MC;
    k_final<<<(total + 255)/256, 256>>>(yo, sbo, ctr, outp, has_ctr);
}

// round 8
// speedup vs baseline: 2.1831x; 1.0930x over previous
#include <cuda_runtime.h>
#include <cstdint>

// ---------------- problem constants ----------------
#define BB    4
#define NPTS  8192
#define MC    1024
#define NSAMP 16
#define CFEAT 64
#define RAD2  0.25f
#define EPSBN 1e-5f

#define FMA2(acc, a, b) asm("fma.rn.f32x2 %0, %1, %2, %0;" : "+l"(acc) : "l"(a), "l"(b))

// ---------------- mma.sync tf32 helpers ----------------
__device__ __forceinline__ float to_tf32(float x) {
    uint32_t r;
    asm("cvt.rna.tf32.f32 %0, %1;" : "=r"(r) : "f"(x));
    return __uint_as_float(r);
}
__device__ __forceinline__ void mma8(float* d, const uint32_t* a, const uint32_t* b) {
    asm volatile(
        "mma.sync.aligned.m16n8k8.row.col.f32.tf32.tf32.f32 "
        "{%0,%1,%2,%3}, {%4,%5,%6,%7}, {%8,%9}, {%0,%1,%2,%3};"
        : "+f"(d[0]), "+f"(d[1]), "+f"(d[2]), "+f"(d[3])
        : "r"(a[0]), "r"(a[1]), "r"(a[2]), "r"(a[3]), "r"(b[0]), "r"(b[1]));
}

#define TSTR   36
#define TILEF  (128*TSTR)
#define MMA_SMEM_BYTES (2*2*TILEF*4)

// ---------------- scratch ----------------
static __device__ float g_featin[(size_t)BB*67*NPTS];
static __device__ float g_y1[(size_t)BB*64*NPTS];
static __device__ float g_y2[(size_t)BB*128*NPTS];
static __device__ float g_y3[(size_t)BB*256*NPTS];
static __device__ float g_nft[(size_t)BB*NPTS*256];
static __device__ int   g_idx1[BB*MC*NSAMP];
static __device__ int   g_idx2[BB*MC*NSAMP];
static __device__ float g_ip[(size_t)BB*259*MC*NSAMP];
static __device__ float g_q[(size_t)BB*8*MC*NSAMP];
static __device__ float g_k[(size_t)BB*8*MC*NSAMP];
static __device__ float g_P[(size_t)BB*NSAMP*MC*MC];
static __device__ float g_v[(size_t)BB*256*MC*NSAMP];
static __device__ float g_off[(size_t)BB*256*MC*NSAMP];
static __device__ float g_yf[(size_t)BB*256*MC*NSAMP];
static __device__ float g_pool[(size_t)BB*256*MC];
static __device__ float g_yo[(size_t)BB*512*MC];
static __device__ float g_st1[2*64], g_st2[2*128], g_st3[2*256], g_stf[2*256], g_sto[2*512];
static __device__ float g_sb1[2*64], g_sb2[2*128], g_sb3[2*256], g_sbf[2*256], g_sbo[2*512];

// ---------------- build concat(xyz^T, features) ----------------
__global__ void k_featin(const float* __restrict__ xyz, const float* __restrict__ feats,
                         float* __restrict__ out)
{
    int i = blockIdx.x * 256 + threadIdx.x;
    if (i >= BB*67*NPTS) return;
    int n  = i % NPTS;
    int ch = (i / NPTS) % 67;
    int b  = i / (NPTS*67);
    float v;
    if (ch < 3) v = xyz[((size_t)b*NPTS + n)*3 + ch];
    else        v = feats[((size_t)b*CFEAT + (ch-3))*NPTS + n];
    out[i] = v;
}

// ======== FFMA2 GEMM (MLP stages + Wo) ========
template<int MODE, int STATS>
__global__ void __launch_bounds__(256, 2)
k_gemm2(const float* __restrict__ W, const float* __restrict__ X,
        float* __restrict__ Y, int Cin, int Cout, int NCOL,
        const float* __restrict__ sb, float* __restrict__ stats)
{
    const int b = blockIdx.z;
    const float* Xb = X + (size_t)b * Cin * NCOL;
    float* Yb = Y + (size_t)b * Cout * NCOL;
    const int col0 = blockIdx.x * 128;
    const int row0 = blockIdx.y * 64;
    __shared__ float Wd[2][16][132];
    __shared__ float Xs[2][16][132];
    const int tid = threadIdx.x;
    const int tx = tid & 15, ty = tid >> 4;
    const int wkk = tid & 15, wrb = tid >> 4;
    const int xcol = tid & 127, xkb = tid >> 7;
    float wreg[4];
    float xreg[8];
    const int nch = (Cin + 15) >> 4;

    {
#pragma unroll
        for (int p = 0; p < 4; p++) {
            float w = 0.f;
            if (wkk < Cin) w = W[(size_t)(row0 + wrb + 16*p)*Cin + wkk];
            wreg[p] = w;
        }
#pragma unroll
        for (int t = 0; t < 8; t++) {
            int cg = xkb + 2*t;
            float v = 0.f;
            if (cg < Cin) {
                v = Xb[(size_t)cg*NCOL + col0 + xcol];
                if (MODE == 1) v = fmaxf(fmaf(v, sb[cg], sb[Cin+cg]), 0.f);
            }
            xreg[t] = v;
        }
    }
#pragma unroll
    for (int p = 0; p < 4; p++) *(float2*)&Wd[0][wkk][2*(wrb+16*p)] = make_float2(wreg[p], wreg[p]);
#pragma unroll
    for (int t = 0; t < 8; t++) Xs[0][xkb + 2*t][xcol] = xreg[t];
    __syncthreads();

    unsigned long long acc[4][4];
#pragma unroll
    for (int i = 0; i < 4; i++)
#pragma unroll
        for (int p = 0; p < 4; p++) acc[i][p] = 0ull;

    for (int c = 0; c < nch; c++) {
        int buf = c & 1;
        if (c + 1 < nch) {
            int k0 = (c + 1) << 4;
#pragma unroll
            for (int p = 0; p < 4; p++) {
                float w = 0.f;
                if (k0 + wkk < Cin) w = W[(size_t)(row0 + wrb + 16*p)*Cin + k0 + wkk];
                wreg[p] = w;
            }
#pragma unroll
            for (int t = 0; t < 8; t++) {
                int cg = k0 + xkb + 2*t;
                float v = 0.f;
                if (cg < Cin) {
                    v = Xb[(size_t)cg*NCOL + col0 + xcol];
                    if (MODE == 1) v = fmaxf(fmaf(v, sb[cg], sb[Cin+cg]), 0.f);
                }
                xreg[t] = v;
            }
        }
#pragma unroll
        for (int kk = 0; kk < 16; kk++) {
            ulonglong2 wa = *(const ulonglong2*)&Wd[buf][kk][ty*8];
            ulonglong2 wb = *(const ulonglong2*)&Wd[buf][kk][ty*8 + 4];
            ulonglong2 xa = *(const ulonglong2*)&Xs[buf][kk][tx*4];
            ulonglong2 xb = *(const ulonglong2*)&Xs[buf][kk][64 + tx*4];
            unsigned long long wp[4] = {wa.x, wa.y, wb.x, wb.y};
            unsigned long long xp[4] = {xa.x, xa.y, xb.x, xb.y};
#pragma unroll
            for (int i = 0; i < 4; i++) {
                FMA2(acc[i][0], wp[i], xp[0]);
                FMA2(acc[i][1], wp[i], xp[1]);
                FMA2(acc[i][2], wp[i], xp[2]);
                FMA2(acc[i][3], wp[i], xp[3]);
            }
        }
        if (c + 1 < nch) {
            int nb = buf ^ 1;
#pragma unroll
            for (int p = 0; p < 4; p++) *(float2*)&Wd[nb][wkk][2*(wrb+16*p)] = make_float2(wreg[p], wreg[p]);
#pragma unroll
            for (int t = 0; t < 8; t++) Xs[nb][xkb + 2*t][xcol] = xreg[t];
            __syncthreads();
        }
    }

#pragma unroll
    for (int i = 0; i < 4; i++) {
        int r = row0 + ty*4 + i;
        float rs = 0.f, rq = 0.f;
        float v[8];
#pragma unroll
        for (int p = 0; p < 4; p++) {
            float lo, hi;
            asm("mov.b64 {%0, %1}, %2;" : "=f"(lo), "=f"(hi) : "l"(acc[i][p]));
            v[p*2] = lo; v[p*2+1] = hi;
            rs += lo + hi; rq += lo*lo + hi*hi;
        }
        *(float4*)&Yb[(size_t)r*NCOL + col0 + tx*4]      = make_float4(v[0], v[1], v[2], v[3]);
        *(float4*)&Yb[(size_t)r*NCOL + col0 + 64 + tx*4] = make_float4(v[4], v[5], v[6], v[7]);
        if (STATS) {
#pragma unroll
            for (int o = 8; o > 0; o >>= 1) {
                rs += __shfl_down_sync(0xffffffffu, rs, o);
                rq += __shfl_down_sync(0xffffffffu, rq, o);
            }
            if (tx == 0) { atomicAdd(&stats[r], rs); atomicAdd(&stats[Cout + r], rq); }
        }
    }
}

// ======== mma.sync tf32 core ========
__device__ __forceinline__ void mma_tile(const float* As, const float* Bs,
                                         float acc[2][8][4], int warp_m, int warp_n,
                                         int g, int t4)
{
#pragma unroll
    for (int ks = 0; ks < 4; ks++) {
        const int kb = ks * 8;
        uint32_t a[2][4];
#pragma unroll
        for (int fm = 0; fm < 2; fm++) {
            const int rm = warp_m*32 + fm*16;
            a[fm][0] = __float_as_uint(As[(rm + g)*TSTR + kb + t4]);
            a[fm][1] = __float_as_uint(As[(rm + 8 + g)*TSTR + kb + t4]);
            a[fm][2] = __float_as_uint(As[(rm + g)*TSTR + kb + 4 + t4]);
            a[fm][3] = __float_as_uint(As[(rm + 8 + g)*TSTR + kb + 4 + t4]);
        }
#pragma unroll
        for (int fn = 0; fn < 8; fn++) {
            const int rn = warp_n*64 + fn*8;
            uint32_t b[2];
            b[0] = __float_as_uint(Bs[(rn + g)*TSTR + kb + t4]);
            b[1] = __float_as_uint(Bs[(rn + g)*TSTR + kb + 4 + t4]);
            mma8(acc[0][fn], a[0], b);
            mma8(acc[1][fn], a[1], b);
        }
    }
}

// ======== attfeat (NT): off[c,j] = sum_n V[c,n] P[j,n] - gf[c,j] ========
__global__ void __launch_bounds__(256, 2)
k_mma_nt(const float* __restrict__ V, const float* __restrict__ P,
         const float* __restrict__ ip, float* __restrict__ off)
{
    extern __shared__ float sm[];
    const int tid = threadIdx.x, wid = tid >> 5, lane = tid & 31;
    const int warp_m = wid >> 1, warp_n = wid & 1;
    const int g = lane >> 2, t4 = lane & 3;
    const int bs = blockIdx.z, slot = bs & 15, b = bs >> 4;
    const float* Vb = V + ((size_t)b*256*NSAMP + slot)*MC;
    const float* Pb = P + ((size_t)(b*NSAMP + slot))*MC*MC;
    const int j0 = blockIdx.x * 128;
    const int c0 = blockIdx.y * 128;

    float acc[2][8][4];
#pragma unroll
    for (int i = 0; i < 2; i++)
#pragma unroll
        for (int j = 0; j < 8; j++)
#pragma unroll
            for (int p = 0; p < 4; p++) acc[i][j][p] = 0.f;

    float4 pa[4], pb[4];
#pragma unroll
    for (int it = 0; it < 4; it++) {
        int idx = tid + 256*it, row = idx >> 3, f = idx & 7;
        pa[it] = *(const float4*)&Vb[(size_t)(c0+row)*(NSAMP*MC) + 4*f];
        pb[it] = *(const float4*)&Pb[(size_t)(j0+row)*MC + 4*f];
    }
    {
        float* As = sm; float* Bs = sm + TILEF;
#pragma unroll
        for (int it = 0; it < 4; it++) {
            int idx = tid + 256*it, row = idx >> 3, f = idx & 7;
            *(float4*)&As[row*TSTR + 4*f] = make_float4(to_tf32(pa[it].x), to_tf32(pa[it].y),
                                                        to_tf32(pa[it].z), to_tf32(pa[it].w));
            *(float4*)&Bs[row*TSTR + 4*f] = make_float4(to_tf32(pb[it].x), to_tf32(pb[it].y),
                                                        to_tf32(pb[it].z), to_tf32(pb[it].w));
        }
    }
    __syncthreads();

    const int nch = MC / 32;
    for (int c = 0; c < nch; c++) {
        const int buf = c & 1;
        if (c + 1 < nch) {
            const int n0 = (c + 1) * 32;
#pragma unroll
            for (int it = 0; it < 4; it++) {
                int idx = tid + 256*it, row = idx >> 3, f = idx & 7;
                pa[it] = *(const float4*)&Vb[(size_t)(c0+row)*(NSAMP*MC) + n0 + 4*f];
                pb[it] = *(const float4*)&Pb[(size_t)(j0+row)*MC + n0 + 4*f];
            }
        }
        mma_tile(sm + buf*2*TILEF, sm + buf*2*TILEF + TILEF, acc, warp_m, warp_n, g, t4);
        if (c + 1 < nch) {
            const int nb = buf ^ 1;
            float* As = sm + nb*2*TILEF; float* Bs = As + TILEF;
            __syncthreads();
#pragma unroll
            for (int it = 0; it < 4; it++) {
                int idx = tid + 256*it, row = idx >> 3, f = idx & 7;
                *(float4*)&As[row*TSTR + 4*f] = make_float4(to_tf32(pa[it].x), to_tf32(pa[it].y),
                                                            to_tf32(pa[it].z), to_tf32(pa[it].w));
                *(float4*)&Bs[row*TSTR + 4*f] = make_float4(to_tf32(pb[it].x), to_tf32(pb[it].y),
                                                            to_tf32(pb[it].z), to_tf32(pb[it].w));
            }
            __syncthreads();
        }
    }

#pragma unroll
    for (int fm = 0; fm < 2; fm++) {
        const int r0 = c0 + warp_m*32 + fm*16 + g;
        const int r1 = r0 + 8;
        const float* ip0 = ip + (((size_t)b*259 + r0)*NSAMP + slot)*MC;
        const float* ip1 = ip + (((size_t)b*259 + r1)*NSAMP + slot)*MC;
        float* of0 = off + (((size_t)b*256 + r0)*NSAMP + slot)*MC;
        float* of1 = off + (((size_t)b*256 + r1)*NSAMP + slot)*MC;
#pragma unroll
        for (int fn = 0; fn < 8; fn++) {
            const int jj = j0 + warp_n*64 + fn*8 + 2*t4;
            float2 ga = *(const float2*)&ip0[jj];
            float2 gb = *(const float2*)&ip1[jj];
            *(float2*)&of0[jj] = make_float2(acc[fm][fn][0] - ga.x, acc[fm][fn][1] - ga.y);
            *(float2*)&of1[jj] = make_float2(acc[fm][fn][2] - gb.x, acc[fm][fn][3] - gb.y);
        }
    }
}

// ======== NN: Y[b,o,col] = sum_k W[o,k] X[b,k,col] (tf32 mma; Wv / Wf) ========
template<int STATS>
__global__ void __launch_bounds__(256, 2)
k_mma_nn(const float* __restrict__ W, const float* __restrict__ X,
         float* __restrict__ Y, int Cin, int Cout, float* __restrict__ stats)
{
    extern __shared__ float sm[];
    const int tid = threadIdx.x, wid = tid >> 5, lane = tid & 31;
    const int warp_m = wid >> 1, warp_n = wid & 1;
    const int g = lane >> 2, t4 = lane & 3;
    const int b = blockIdx.z;
    const int NCOL = MC * NSAMP;
    const float* Xb = X + (size_t)b * Cin * NCOL;
    const int ncol0 = blockIdx.x * 128;
    const int row0 = blockIdx.y * 128;
    const bool al4 = (Cin & 3) == 0;

    float acc[2][8][4];
#pragma unroll
    for (int i = 0; i < 2; i++)
#pragma unroll
        for (int j = 0; j < 8; j++)
#pragma unroll
            for (int p = 0; p < 4; p++) acc[i][j][p] = 0.f;

    float4 pa[4], pb[4];
    const int nch = (Cin + 31) >> 5;

    auto loadA = [&](int k0, float4* dst) {
#pragma unroll
        for (int it = 0; it < 4; it++) {
            int idx = tid + 256*it, row = idx >> 3, f = idx & 7;
            int k = k0 + 4*f;
            const float* wr = &W[(size_t)(row0+row)*Cin];
            float4 w4;
            if (al4 && k + 3 < Cin) w4 = *(const float4*)&wr[k];
            else {
                w4.x = (k+0 < Cin) ? wr[k+0] : 0.f;
                w4.y = (k+1 < Cin) ? wr[k+1] : 0.f;
                w4.z = (k+2 < Cin) ? wr[k+2] : 0.f;
                w4.w = (k+3 < Cin) ? wr[k+3] : 0.f;
            }
            dst[it] = w4;
        }
    };
    auto loadB = [&](int k0, float4* dst) {
#pragma unroll
        for (int it = 0; it < 4; it++) {
            int kk = k0 + lane;
            int n4 = (tid >> 5) + 8*it;
            float4 x4 = make_float4(0.f, 0.f, 0.f, 0.f);
            if (kk < Cin) x4 = *(const float4*)&Xb[(size_t)kk*NCOL + ncol0 + 4*n4];
            dst[it] = x4;
        }
    };
    auto storeT = [&](int bufbase, const float4* va, const float4* vb) {
        float* As = sm + bufbase; float* Bs = As + TILEF;
#pragma unroll
        for (int it = 0; it < 4; it++) {
            int idx = tid + 256*it, row = idx >> 3, f = idx & 7;
            *(float4*)&As[row*TSTR + 4*f] = make_float4(to_tf32(va[it].x), to_tf32(va[it].y),
                                                        to_tf32(va[it].z), to_tf32(va[it].w));
            int kk = lane;
            int n4 = (tid >> 5) + 8*it;
            Bs[(4*n4 + 0)*TSTR + kk] = to_tf32(vb[it].x);
            Bs[(4*n4 + 1)*TSTR + kk] = to_tf32(vb[it].y);
            Bs[(4*n4 + 2)*TSTR + kk] = to_tf32(vb[it].z);
            Bs[(4*n4 + 3)*TSTR + kk] = to_tf32(vb[it].w);
        }
    };

    loadA(0, pa); loadB(0, pb);
    storeT(0, pa, pb);
    __syncthreads();

    for (int c = 0; c < nch; c++) {
        const int buf = c & 1;
        if (c + 1 < nch) { loadA((c+1)*32, pa); loadB((c+1)*32, pb); }
        mma_tile(sm + buf*2*TILEF, sm + buf*2*TILEF + TILEF, acc, warp_m, warp_n, g, t4);
        if (c + 1 < nch) {
            __syncthreads();
            storeT((buf^1)*2*TILEF, pa, pb);
            __syncthreads();
        }
    }

#pragma unroll
    for (int fm = 0; fm < 2; fm++) {
        const int r0 = row0 + warp_m*32 + fm*16 + g;
        const int r1 = r0 + 8;
        float* y0 = Y + ((size_t)b*Cout + r0)*NCOL + ncol0;
        float* y1 = Y + ((size_t)b*Cout + r1)*NCOL + ncol0;
        float s0 = 0.f, q0 = 0.f, s1 = 0.f, q1 = 0.f;
#pragma unroll
        for (int fn = 0; fn < 8; fn++) {
            const int jj = warp_n*64 + fn*8 + 2*t4;
            float d0 = acc[fm][fn][0], d1 = acc[fm][fn][1];
            float d2 = acc[fm][fn][2], d3 = acc[fm][fn][3];
            *(float2*)&y0[jj] = make_float2(d0, d1);
            *(float2*)&y1[jj] = make_float2(d2, d3);
            if (STATS) {
                s0 += d0 + d1; q0 += d0*d0 + d1*d1;
                s1 += d2 + d3; q1 += d2*d2 + d3*d3;
            }
        }
        if (STATS) {
#pragma unroll
            for (int o = 1; o < 4; o <<= 1) {
                s0 += __shfl_xor_sync(0xffffffffu, s0, o);
                q0 += __shfl_xor_sync(0xffffffffu, q0, o);
                s1 += __shfl_xor_sync(0xffffffffu, s1, o);
                q1 += __shfl_xor_sync(0xffffffffu, q1, o);
            }
            if (t4 == 0) {
                atomicAdd(&stats[r0], s0); atomicAdd(&stats[Cout + r0], q0);
                atomicAdd(&stats[r1], s1); atomicAdd(&stats[Cout + r1], q1);
            }
        }
    }
}

// ---------------- fused q+k projection ----------------
__global__ void k_qk(const float* __restrict__ Wq, const float* __restrict__ Wk,
                     const float* __restrict__ X, float* __restrict__ q,
                     float* __restrict__ k)
{
    const int b = blockIdx.y;
    const int NCOL = MC*NSAMP;
    const float* Xb = X + (size_t)b * 259 * NCOL;
    __shared__ float Ws[16][260];
    for (int i = threadIdx.x; i < 8*259; i += 128) {
        int r = i / 259, c = i % 259;
        Ws[r][c] = Wq[i];
        Ws[r+8][c] = Wk[i];
    }
    __syncthreads();
    int col = blockIdx.x * 128 + threadIdx.x;
    float acc[16];
#pragma unroll
    for (int o = 0; o < 16; o++) acc[o] = 0.f;
    for (int c = 0; c < 259; c++) {
        float xv = Xb[(size_t)c*NCOL + col];
#pragma unroll
        for (int o = 0; o < 16; o++) acc[o] = fmaf(Ws[o][c], xv, acc[o]);
    }
#pragma unroll
    for (int o = 0; o < 8; o++) {
        q[((size_t)b*8 + o)*NCOL + col] = acc[o];
        k[((size_t)b*8 + o)*NCOL + col] = acc[o+8];
    }
}

// ---------------- BN finalize ----------------
__global__ void k_fin(const float* __restrict__ stats, const float* __restrict__ g,
                      const float* __restrict__ be, float* __restrict__ sb,
                      int Cc, float invcnt)
{
    int c = blockIdx.x * 64 + threadIdx.x;
    if (c >= Cc) return;
    float mu  = stats[c] * invcnt;
    float var = stats[Cc + c] * invcnt - mu*mu;
    float s = g[c] * rsqrtf(var + EPSBN);
    sb[c] = s;
    sb[Cc + c] = be[c] - mu * s;
}

// ---------------- ball query ----------------
__global__ void k_bq(const float* __restrict__ src, const float* __restrict__ ctr,
                     int* __restrict__ out, int NSRC)
{
    int gw = (blockIdx.x * blockDim.x + threadIdx.x) >> 5;
    int lane = threadIdx.x & 31;
    __shared__ int lists[8][NSAMP];
    int* list = lists[threadIdx.x >> 5];
    if (gw >= BB*MC) return;
    int b = gw / MC, m = gw % MC;
    float cx = ctr[((size_t)b*MC + m)*3 + 0];
    float cy = ctr[((size_t)b*MC + m)*3 + 1];
    float cz = ctr[((size_t)b*MC + m)*3 + 2];
    int count = 0;
    for (int base = 0; base < NSRC; base += 32) {
        int n = base + lane;
        bool ok = false;
        if (n < NSRC) {
            float dx = src[((size_t)b*NSRC + n)*3 + 0] - cx;
            float dy = src[((size_t)b*NSRC + n)*3 + 1] - cy;
            float dz = src[((size_t)b*NSRC + n)*3 + 2] - cz;
            ok = (dx*dx + dy*dy + dz*dz) < RAD2;
        }
        unsigned mk = __ballot_sync(0xffffffffu, ok);
        if (ok) {
            int pos = count + __popc(mk & ((1u << lane) - 1u));
            if (pos < NSAMP) list[pos] = n;
        }
        count += __popc(mk);
        if (count >= NSAMP) break;
    }
    __syncwarp();
    if (lane < NSAMP) {
        int v;
        if (count == 0) v = 0;
        else v = (lane < count) ? list[lane] : list[0];
        out[((size_t)b*MC + m)*NSAMP + lane] = v;
    }
}

// ---------------- new_features transpose with affine+relu ----------------
__global__ void k_nft(const float* __restrict__ y3, const float* __restrict__ sb3,
                      float* __restrict__ nft)
{
    int b = blockIdx.z;
    int n0 = blockIdx.x * 32, c0 = blockIdx.y * 32;
    __shared__ float t[32][33];
#pragma unroll
    for (int i = 0; i < 4; i++) {
        int c = c0 + threadIdx.y + i*8;
        int n = n0 + threadIdx.x;
        float v = y3[((size_t)b*256 + c)*NPTS + n];
        v = fmaxf(fmaf(v, sb3[c], sb3[256 + c]), 0.f);
        t[threadIdx.y + i*8][threadIdx.x] = v;
    }
    __syncthreads();
#pragma unroll
    for (int i = 0; i < 4; i++) {
        int n = n0 + threadIdx.y + i*8;
        int c = c0 + threadIdx.x;
        nft[((size_t)b*NPTS + n)*256 + c] = t[threadIdx.x][threadIdx.y + i*8];
    }
}

// ---------------- build ip ----------------
__global__ void k_ip(const float* __restrict__ nft, const int* __restrict__ idx1,
                     const int* __restrict__ idx2, const float* __restrict__ xyz,
                     const float* __restrict__ ctr, float* __restrict__ ip)
{
    int bz = blockIdx.x;
    int cblk = bz & 31;
    int slot = (bz >> 5) & 15;
    int b    = bz >> 9;
    __shared__ float s[256][33];
    int warp = threadIdx.x >> 5, lane = threadIdx.x & 31;
#pragma unroll
    for (int w = 0; w < 4; w++) {
        int center = cblk*32 + warp*4 + w;
        int id = idx1[((size_t)b*MC + center)*NSAMP + slot];
        const float* srcp = nft + ((size_t)b*NPTS + id)*256;
#pragma unroll
        for (int t = 0; t < 8; t++) s[lane + t*32][warp*4 + w] = srcp[lane + t*32];
    }
    __syncthreads();
    int center = threadIdx.x & 31, chb = threadIdx.x >> 5;
#pragma unroll
    for (int t = 0; t < 32; t++) {
        int ch = chb + t*8;
        ip[(((size_t)b*259 + ch)*NSAMP + slot)*MC + cblk*32 + center] = s[ch][center];
    }
    if (threadIdx.x < 96) {
        int d = threadIdx.x / 32;
        int cc = threadIdx.x & 31;
        int ctr_i = cblk*32 + cc;
        int i1 = idx1[((size_t)b*MC + ctr_i)*NSAMP + slot];
        int i2 = idx2[((size_t)b*MC + ctr_i)*NSAMP + slot];
        float r = ctr[((size_t)b*MC + i2)*3 + d] - xyz[((size_t)b*NPTS + i1)*3 + d];
        ip[(((size_t)b*259 + 256 + d)*NSAMP + slot)*MC + ctr_i] = r;
    }
}

// ---------------- attention: warp-per-column softmax ----------------
__global__ void __launch_bounds__(256)
k_att(const float* __restrict__ q, const float* __restrict__ k,
      float* __restrict__ P)
{
    int bx = blockIdx.x;
    int jblk = bx & 127;          // MC/8
    int slot = (bx >> 7) & 15;
    int b = bx >> 11;
    int wid = threadIdx.x >> 5, lane = threadIdx.x & 31;
    int j = jblk*8 + wid;
    const float* qb = q + ((size_t)b*8*NSAMP + slot)*MC;
    const float* kb = k + ((size_t)b*8*NSAMP + slot)*MC;
    float tq = (lane < 8) ? qb[(size_t)lane*NSAMP*MC + j] : 0.f;
    float qv[8];
#pragma unroll
    for (int c = 0; c < 8; c++) qv[c] = __shfl_sync(0xffffffffu, tq, c);

    float s[32];
#pragma unroll
    for (int it = 0; it < 32; it++) {
        int n = it*32 + lane;
        float a = 0.f;
#pragma unroll
        for (int c = 0; c < 8; c++) a = fmaf(kb[(size_t)c*NSAMP*MC + n], qv[c], a);
        s[it] = a;
    }
    float mx = s[0];
#pragma unroll
    for (int it = 1; it < 32; it++) mx = fmaxf(mx, s[it]);
#pragma unroll
    for (int o = 16; o > 0; o >>= 1) mx = fmaxf(mx, __shfl_xor_sync(0xffffffffu, mx, o));
    float sum = 0.f;
#pragma unroll
    for (int it = 0; it < 32; it++) { s[it] = __expf(s[it] - mx); sum += s[it]; }
#pragma unroll
    for (int o = 16; o > 0; o >>= 1) sum += __shfl_xor_sync(0xffffffffu, sum, o);
    float inv = 1.f / sum;
    float* Pr = P + (((size_t)(b*NSAMP + slot))*MC + j)*MC;
#pragma unroll
    for (int it = 0; it < 32; it++) Pr[it*32 + lane] = s[it] * inv;
}

// ---------------- relu(affine(yf)) + gf residual, max-pool over slot ----------------
__global__ void k_pool(const float* __restrict__ yf, const float* __restrict__ sbf,
                       const float* __restrict__ ip, float* __restrict__ pool)
{
    int i = blockIdx.x * 256 + threadIdx.x;
    if (i >= BB*256*MC) return;
    int center = i & (MC-1);
    int c = (i >> 10) & 255;
    int b = i >> 18;
    float s = sbf[c], bi = sbf[256 + c];
    float mx = -1e30f;
#pragma unroll
    for (int slot = 0; slot < NSAMP; slot++) {
        float v = fmaxf(fmaf(yf[(((size_t)b*256 + c)*NSAMP + slot)*MC + center], s, bi), 0.f);
        v += ip[(((size_t)b*259 + c)*NSAMP + slot)*MC + center];
        mx = fmaxf(mx, v);
    }
    pool[((size_t)b*256 + c)*MC + center] = mx;
}

// ---------------- final ----------------
__global__ void k_final(const float* __restrict__ yo, const float* __restrict__ sbo,
                        const float* __restrict__ ctr, float* __restrict__ out, int has_ctr)
{
    int off0 = has_ctr ? BB*MC*3 : 0;
    int total = off0 + BB*512*MC;
    int i = blockIdx.x * 256 + threadIdx.x;
    if (i >= total) return;
    if (i < off0) { out[i] = ctr[i]; return; }
    int j = i - off0;
    int ch = (j >> 10) & 511;
    out[i] = fmaxf(fmaf(yo[j], sbo[ch], sbo[512 + ch]), 0.f);
}

// ---------------- host launch ----------------
extern "C" void kernel_launch(void* const* d_in, const int* in_sizes, int n_in,
                              void* d_out, int out_size)
{
    const float* xyz   = (const float*)d_in[0];
    const float* feats = (const float*)d_in[1];
    const float* ctr   = (const float*)d_in[2];
    const float* W1 = (const float*)d_in[3];
    const float* g1 = (const float*)d_in[4];
    const float* b1 = (const float*)d_in[5];
    const float* W2 = (const float*)d_in[6];
    const float* g2 = (const float*)d_in[7];
    const float* b2 = (const float*)d_in[8];
    const float* W3 = (const float*)d_in[9];
    const float* g3 = (const float*)d_in[10];
    const float* b3 = (const float*)d_in[11];
    const float* Wq = (const float*)d_in[12];
    const float* Wk = (const float*)d_in[13];
    const float* Wv = (const float*)d_in[14];
    const float* Wf = (const float*)d_in[15];
    const float* gp = (const float*)d_in[16];
    const float* bp = (const float*)d_in[17];
    const float* Wo = (const float*)d_in[18];
    const float* go = (const float*)d_in[19];
    const float* bo = (const float*)d_in[20];
    float* outp = (float*)d_out;

    float *featin, *y1, *y2, *y3, *nft, *ip, *qb, *kb, *vb, *Pb, *offb, *yf, *pool, *yo;
    int *idx1, *idx2;
    float *st1, *st2, *st3, *stf, *sto, *sb1, *sb2, *sb3, *sbf, *sbo;
    cudaGetSymbolAddress((void**)&featin, g_featin);
    cudaGetSymbolAddress((void**)&y1, g_y1);
    cudaGetSymbolAddress((void**)&y2, g_y2);
    cudaGetSymbolAddress((void**)&y3, g_y3);
    cudaGetSymbolAddress((void**)&nft, g_nft);
    cudaGetSymbolAddress((void**)&idx1, g_idx1);
    cudaGetSymbolAddress((void**)&idx2, g_idx2);
    cudaGetSymbolAddress((void**)&ip, g_ip);
    cudaGetSymbolAddress((void**)&qb, g_q);
    cudaGetSymbolAddress((void**)&kb, g_k);
    cudaGetSymbolAddress((void**)&vb, g_v);
    cudaGetSymbolAddress((void**)&Pb, g_P);
    cudaGetSymbolAddress((void**)&offb, g_off);
    cudaGetSymbolAddress((void**)&yf, g_yf);
    cudaGetSymbolAddress((void**)&pool, g_pool);
    cudaGetSymbolAddress((void**)&yo, g_yo);
    cudaGetSymbolAddress((void**)&st1, g_st1);
    cudaGetSymbolAddress((void**)&st2, g_st2);
    cudaGetSymbolAddress((void**)&st3, g_st3);
    cudaGetSymbolAddress((void**)&stf, g_stf);
    cudaGetSymbolAddress((void**)&sto, g_sto);
    cudaGetSymbolAddress((void**)&sb1, g_sb1);
    cudaGetSymbolAddress((void**)&sb2, g_sb2);
    cudaGetSymbolAddress((void**)&sb3, g_sb3);
    cudaGetSymbolAddress((void**)&sbf, g_sbf);
    cudaGetSymbolAddress((void**)&sbo, g_sbo);

    cudaFuncSetAttribute(k_mma_nt, cudaFuncAttributeMaxDynamicSharedMemorySize, MMA_SMEM_BYTES);
    cudaFuncSetAttribute(k_mma_nn<0>, cudaFuncAttributeMaxDynamicSharedMemorySize, MMA_SMEM_BYTES);
    cudaFuncSetAttribute(k_mma_nn<1>, cudaFuncAttributeMaxDynamicSharedMemorySize, MMA_SMEM_BYTES);

    cudaMemsetAsync(st1, 0, sizeof(float)*2*64,  0);
    cudaMemsetAsync(st2, 0, sizeof(float)*2*128, 0);
    cudaMemsetAsync(st3, 0, sizeof(float)*2*256, 0);
    cudaMemsetAsync(stf, 0, sizeof(float)*2*256, 0);
    cudaMemsetAsync(sto, 0, sizeof(float)*2*512, 0);

    k_featin<<<(BB*67*NPTS + 255)/256, 256>>>(xyz, feats, featin);

    // MLP (FFMA2, fp32 — trunk precision)
    k_gemm2<0,1><<<dim3(NPTS/128, 1, BB), 256>>>(W1, featin, y1, 67, 64, NPTS, nullptr, st1);
    k_fin<<<1, 64>>>(st1, g1, b1, sb1, 64, 1.f/(BB*NPTS));
    k_gemm2<1,1><<<dim3(NPTS/128, 2, BB), 256>>>(W2, y1, y2, 64, 128, NPTS, sb1, st2);
    k_fin<<<2, 64>>>(st2, g2, b2, sb2, 128, 1.f/(BB*NPTS));
    k_gemm2<1,1><<<dim3(NPTS/128, 4, BB), 256>>>(W3, y2, y3, 128, 256, NPTS, sb2, st3);
    k_fin<<<4, 64>>>(st3, g3, b3, sb3, 256, 1.f/(BB*NPTS));

    k_nft<<<dim3(NPTS/32, 8, BB), dim3(32, 8)>>>(y3, sb3, nft);

    k_bq<<<(BB*MC*32 + 255)/256, 256>>>(xyz, ctr, idx1, NPTS);
    k_bq<<<(BB*MC*32 + 255)/256, 256>>>(ctr, ctr, idx2, MC);

    k_ip<<<BB*16*32, 256>>>(nft, idx1, idx2, xyz, ctr, ip);

    // q, k (fused FFMA), v (tf32 mma)
    k_qk<<<dim3(MC*NSAMP/128, BB), 128>>>(Wq, Wk, ip, qb, kb);
    k_mma_nn<0><<<dim3(128, 2, BB), 256, MMA_SMEM_BYTES>>>(Wv, ip, vb, 259, 256, nullptr);

    // attention: warp-per-j softmax, then V P^T (tf32 mma)
    k_att<<<BB*NSAMP*(MC/8), 256>>>(qb, kb, Pb);
    k_mma_nt<<<dim3(8, 2, BB*NSAMP), 256, MMA_SMEM_BYTES>>>(vb, Pb, ip, offb);

    // Wf (tf32 mma + BN stats), pool
    k_mma_nn<1><<<dim3(128, 2, BB), 256, MMA_SMEM_BYTES>>>(Wf, offb, yf, 256, 256, stf);
    k_fin<<<4, 64>>>(stf, gp, bp, sbf, 256, 1.f/(BB*MC*NSAMP));
    k_pool<<<(BB*256*MC + 255)/256, 256>>>(yf, sbf, ip, pool);

    // output conv (FFMA2, fp32)
    k_gemm2<0,1><<<dim3(MC/128, 8, BB), 256>>>(Wo, pool, yo, 256, 512, MC, nullptr, sto);
    k_fin<<<8, 64>>>(sto, go, bo, sbo, 512, 1.f/(BB*MC));

    int has_ctr = (out_size == BB*MC*3 + BB*512*MC) ? 1 : 0;
    int total = (has_ctr ? BB*MC*3 : 0) + BB*512*MC;
    k_final<<<(total + 255)/256, 256>>>(yo, sbo, ctr, outp, has_ctr);
}

// round 9
// speedup vs baseline: 2.3323x; 1.0683x over previous
#include <cuda_runtime.h>
#include <cstdint>

// ---------------- problem constants ----------------
#define BB    4
#define NPTS  8192
#define MC    1024
#define NSAMP 16
#define CFEAT 64
#define RAD2  0.25f
#define EPSBN 1e-5f

#define FMA2(acc, a, b) asm("fma.rn.f32x2 %0, %1, %2, %0;" : "+l"(acc) : "l"(a), "l"(b))

// ---------------- mma.sync tf32 helpers ----------------
__device__ __forceinline__ float to_tf32(float x) {
    uint32_t r;
    asm("cvt.rna.tf32.f32 %0, %1;" : "=r"(r) : "f"(x));
    return __uint_as_float(r);
}
__device__ __forceinline__ void mma8(float* d, const uint32_t* a, const uint32_t* b) {
    asm volatile(
        "mma.sync.aligned.m16n8k8.row.col.f32.tf32.tf32.f32 "
        "{%0,%1,%2,%3}, {%4,%5,%6,%7}, {%8,%9}, {%0,%1,%2,%3};"
        : "+f"(d[0]), "+f"(d[1]), "+f"(d[2]), "+f"(d[3])
        : "r"(a[0]), "r"(a[1]), "r"(a[2]), "r"(a[3]), "r"(b[0]), "r"(b[1]));
}

#define TSTR   36
#define ATILE  (256*TSTR)
#define BTILE  (128*TSTR)
#define MMA_SMEM_BYTES ((2*ATILE + 2*BTILE)*4)   // 110592

// ---------------- scratch ----------------
static __device__ float g_featin[(size_t)BB*67*NPTS];
static __device__ float g_y1[(size_t)BB*64*NPTS];
static __device__ float g_y2[(size_t)BB*128*NPTS];
static __device__ float g_y3[(size_t)BB*256*NPTS];
static __device__ float g_nft[(size_t)BB*NPTS*256];
static __device__ int   g_idx1[BB*MC*NSAMP];
static __device__ int   g_idx2[BB*MC*NSAMP];
static __device__ float g_ip[(size_t)BB*259*MC*NSAMP];
static __device__ float g_q[(size_t)BB*8*MC*NSAMP];
static __device__ float g_k[(size_t)BB*8*MC*NSAMP];
static __device__ float g_P[(size_t)BB*NSAMP*MC*MC];
static __device__ float g_v[(size_t)BB*256*MC*NSAMP];
static __device__ float g_off[(size_t)BB*256*MC*NSAMP];
static __device__ float g_yf[(size_t)BB*256*MC*NSAMP];
static __device__ float g_pool[(size_t)BB*256*MC];
static __device__ float g_yo[(size_t)BB*512*MC];
static __device__ float g_st1[2*64], g_st2[2*128], g_st3[2*256], g_stf[2*256], g_sto[2*512];
static __device__ float g_sb1[2*64], g_sb2[2*128], g_sb3[2*256], g_sbf[2*256], g_sbo[2*512];

// ---------------- build concat(xyz^T, features) ----------------
__global__ void k_featin(const float* __restrict__ xyz, const float* __restrict__ feats,
                         float* __restrict__ out)
{
    int i = blockIdx.x * 256 + threadIdx.x;
    if (i >= BB*67*NPTS) return;
    int n  = i % NPTS;
    int ch = (i / NPTS) % 67;
    int b  = i / (NPTS*67);
    float v;
    if (ch < 3) v = xyz[((size_t)b*NPTS + n)*3 + ch];
    else        v = feats[((size_t)b*CFEAT + (ch-3))*NPTS + n];
    out[i] = v;
}

// ======== FFMA2 GEMM (MLP stages + Wo) ========
template<int MODE, int STATS>
__global__ void __launch_bounds__(256, 2)
k_gemm2(const float* __restrict__ W, const float* __restrict__ X,
        float* __restrict__ Y, int Cin, int Cout, int NCOL,
        const float* __restrict__ sb, float* __restrict__ stats)
{
    const int b = blockIdx.z;
    const float* Xb = X + (size_t)b * Cin * NCOL;
    float* Yb = Y + (size_t)b * Cout * NCOL;
    const int col0 = blockIdx.x * 128;
    const int row0 = blockIdx.y * 64;
    __shared__ float Wd[2][16][132];
    __shared__ float Xs[2][16][132];
    const int tid = threadIdx.x;
    const int tx = tid & 15, ty = tid >> 4;
    const int wkk = tid & 15, wrb = tid >> 4;
    const int xcol = tid & 127, xkb = tid >> 7;
    float wreg[4];
    float xreg[8];
    const int nch = (Cin + 15) >> 4;

    {
#pragma unroll
        for (int p = 0; p < 4; p++) {
            float w = 0.f;
            if (wkk < Cin) w = W[(size_t)(row0 + wrb + 16*p)*Cin + wkk];
            wreg[p] = w;
        }
#pragma unroll
        for (int t = 0; t < 8; t++) {
            int cg = xkb + 2*t;
            float v = 0.f;
            if (cg < Cin) {
                v = Xb[(size_t)cg*NCOL + col0 + xcol];
                if (MODE == 1) v = fmaxf(fmaf(v, sb[cg], sb[Cin+cg]), 0.f);
            }
            xreg[t] = v;
        }
    }
#pragma unroll
    for (int p = 0; p < 4; p++) *(float2*)&Wd[0][wkk][2*(wrb+16*p)] = make_float2(wreg[p], wreg[p]);
#pragma unroll
    for (int t = 0; t < 8; t++) Xs[0][xkb + 2*t][xcol] = xreg[t];
    __syncthreads();

    unsigned long long acc[4][4];
#pragma unroll
    for (int i = 0; i < 4; i++)
#pragma unroll
        for (int p = 0; p < 4; p++) acc[i][p] = 0ull;

    for (int c = 0; c < nch; c++) {
        int buf = c & 1;
        if (c + 1 < nch) {
            int k0 = (c + 1) << 4;
#pragma unroll
            for (int p = 0; p < 4; p++) {
                float w = 0.f;
                if (k0 + wkk < Cin) w = W[(size_t)(row0 + wrb + 16*p)*Cin + k0 + wkk];
                wreg[p] = w;
            }
#pragma unroll
            for (int t = 0; t < 8; t++) {
                int cg = k0 + xkb + 2*t;
                float v = 0.f;
                if (cg < Cin) {
                    v = Xb[(size_t)cg*NCOL + col0 + xcol];
                    if (MODE == 1) v = fmaxf(fmaf(v, sb[cg], sb[Cin+cg]), 0.f);
                }
                xreg[t] = v;
            }
        }
#pragma unroll
        for (int kk = 0; kk < 16; kk++) {
            ulonglong2 wa = *(const ulonglong2*)&Wd[buf][kk][ty*8];
            ulonglong2 wb = *(const ulonglong2*)&Wd[buf][kk][ty*8 + 4];
            ulonglong2 xa = *(const ulonglong2*)&Xs[buf][kk][tx*4];
            ulonglong2 xb = *(const ulonglong2*)&Xs[buf][kk][64 + tx*4];
            unsigned long long wp[4] = {wa.x, wa.y, wb.x, wb.y};
            unsigned long long xp[4] = {xa.x, xa.y, xb.x, xb.y};
#pragma unroll
            for (int i = 0; i < 4; i++) {
                FMA2(acc[i][0], wp[i], xp[0]);
                FMA2(acc[i][1], wp[i], xp[1]);
                FMA2(acc[i][2], wp[i], xp[2]);
                FMA2(acc[i][3], wp[i], xp[3]);
            }
        }
        if (c + 1 < nch) {
            int nb = buf ^ 1;
#pragma unroll
            for (int p = 0; p < 4; p++) *(float2*)&Wd[nb][wkk][2*(wrb+16*p)] = make_float2(wreg[p], wreg[p]);
#pragma unroll
            for (int t = 0; t < 8; t++) Xs[nb][xkb + 2*t][xcol] = xreg[t];
            __syncthreads();
        }
    }

#pragma unroll
    for (int i = 0; i < 4; i++) {
        int r = row0 + ty*4 + i;
        float rs = 0.f, rq = 0.f;
        float v[8];
#pragma unroll
        for (int p = 0; p < 4; p++) {
            float lo, hi;
            asm("mov.b64 {%0, %1}, %2;" : "=f"(lo), "=f"(hi) : "l"(acc[i][p]));
            v[p*2] = lo; v[p*2+1] = hi;
            rs += lo + hi; rq += lo*lo + hi*hi;
        }
        *(float4*)&Yb[(size_t)r*NCOL + col0 + tx*4]      = make_float4(v[0], v[1], v[2], v[3]);
        *(float4*)&Yb[(size_t)r*NCOL + col0 + 64 + tx*4] = make_float4(v[4], v[5], v[6], v[7]);
        if (STATS) {
#pragma unroll
            for (int o = 8; o > 0; o >>= 1) {
                rs += __shfl_down_sync(0xffffffffu, rs, o);
                rq += __shfl_down_sync(0xffffffffu, rq, o);
            }
            if (tx == 0) { atomicAdd(&stats[r], rs); atomicAdd(&stats[Cout + r], rq); }
        }
    }
}

// ======== mma.sync tf32 core, 64x64 warp tile (fm=4) ========
// As: 256 rows x 32k, Bs: 128 rows x 32k, both k-contiguous, stride TSTR.
__device__ __forceinline__ void mma_tile4(const float* As, const float* Bs,
                                          float acc[4][8][4], int warp_m, int warp_n,
                                          int g, int t4)
{
#pragma unroll
    for (int ks = 0; ks < 4; ks++) {
        const int kb = ks * 8;
        uint32_t a[4][4];
#pragma unroll
        for (int fm = 0; fm < 4; fm++) {
            const int rm = warp_m*64 + fm*16;
            a[fm][0] = __float_as_uint(As[(rm + g)*TSTR + kb + t4]);
            a[fm][1] = __float_as_uint(As[(rm + 8 + g)*TSTR + kb + t4]);
            a[fm][2] = __float_as_uint(As[(rm + g)*TSTR + kb + 4 + t4]);
            a[fm][3] = __float_as_uint(As[(rm + 8 + g)*TSTR + kb + 4 + t4]);
        }
#pragma unroll
        for (int fn = 0; fn < 8; fn++) {
            const int rn = warp_n*64 + fn*8;
            uint32_t b[2];
            b[0] = __float_as_uint(Bs[(rn + g)*TSTR + kb + t4]);
            b[1] = __float_as_uint(Bs[(rn + g)*TSTR + kb + 4 + t4]);
            mma8(acc[0][fn], a[0], b);
            mma8(acc[1][fn], a[1], b);
            mma8(acc[2][fn], a[2], b);
            mma8(acc[3][fn], a[3], b);
        }
    }
}

// ======== attfeat (NT): off[c,j] = sum_n V[c,n] P[j,n] - gf[c,j] ========
// CTA tile: 256 c x 128 j.  8 warps = 4(m) x 2(n), warp tile 64x64.
__global__ void __launch_bounds__(256, 1)
k_mma_nt(const float* __restrict__ V, const float* __restrict__ P,
         const float* __restrict__ ip, float* __restrict__ off)
{
    extern __shared__ float sm[];
    const int tid = threadIdx.x, wid = tid >> 5, lane = tid & 31;
    const int warp_m = wid >> 1, warp_n = wid & 1;
    const int g = lane >> 2, t4 = lane & 3;
    const int bs = blockIdx.z, slot = bs & 15, b = bs >> 4;
    const float* Vb = V + ((size_t)b*256*NSAMP + slot)*MC;
    const float* Pb = P + ((size_t)(b*NSAMP + slot))*MC*MC;
    const int j0 = blockIdx.x * 128;

    float acc[4][8][4];
#pragma unroll
    for (int i = 0; i < 4; i++)
#pragma unroll
        for (int j = 0; j < 8; j++)
#pragma unroll
            for (int p = 0; p < 4; p++) acc[i][j][p] = 0.f;

    float4 pa[8], pb[4];
    auto loadA = [&](int n0) {
#pragma unroll
        for (int it = 0; it < 8; it++) {
            int idx = tid + 256*it, row = idx >> 3, f = idx & 7;
            pa[it] = *(const float4*)&Vb[(size_t)row*(NSAMP*MC) + n0 + 4*f];
        }
    };
    auto loadB = [&](int n0) {
#pragma unroll
        for (int it = 0; it < 4; it++) {
            int idx = tid + 256*it, row = idx >> 3, f = idx & 7;
            pb[it] = *(const float4*)&Pb[(size_t)(j0+row)*MC + n0 + 4*f];
        }
    };
    auto storeT = [&](int buf) {
        float* As = sm + buf*ATILE;
        float* Bs = sm + 2*ATILE + buf*BTILE;
#pragma unroll
        for (int it = 0; it < 8; it++) {
            int idx = tid + 256*it, row = idx >> 3, f = idx & 7;
            *(float4*)&As[row*TSTR + 4*f] = make_float4(to_tf32(pa[it].x), to_tf32(pa[it].y),
                                                        to_tf32(pa[it].z), to_tf32(pa[it].w));
        }
#pragma unroll
        for (int it = 0; it < 4; it++) {
            int idx = tid + 256*it, row = idx >> 3, f = idx & 7;
            *(float4*)&Bs[row*TSTR + 4*f] = make_float4(to_tf32(pb[it].x), to_tf32(pb[it].y),
                                                        to_tf32(pb[it].z), to_tf32(pb[it].w));
        }
    };

    loadA(0); loadB(0);
    storeT(0);
    __syncthreads();

    const int nch = MC / 32;
    for (int c = 0; c < nch; c++) {
        const int buf = c & 1;
        if (c + 1 < nch) { loadA((c+1)*32); loadB((c+1)*32); }
        mma_tile4(sm + buf*ATILE, sm + 2*ATILE + buf*BTILE, acc, warp_m, warp_n, g, t4);
        if (c + 1 < nch) {
            __syncthreads();
            storeT(buf ^ 1);
            __syncthreads();
        }
    }

#pragma unroll
    for (int fm = 0; fm < 4; fm++) {
        const int r0 = warp_m*64 + fm*16 + g;
        const int r1 = r0 + 8;
        const float* ip0 = ip + (((size_t)b*259 + r0)*NSAMP + slot)*MC;
        const float* ip1 = ip + (((size_t)b*259 + r1)*NSAMP + slot)*MC;
        float* of0 = off + (((size_t)b*256 + r0)*NSAMP + slot)*MC;
        float* of1 = off + (((size_t)b*256 + r1)*NSAMP + slot)*MC;
#pragma unroll
        for (int fn = 0; fn < 8; fn++) {
            const int jj = j0 + warp_n*64 + fn*8 + 2*t4;
            float2 ga = *(const float2*)&ip0[jj];
            float2 gb = *(const float2*)&ip1[jj];
            *(float2*)&of0[jj] = make_float2(acc[fm][fn][0] - ga.x, acc[fm][fn][1] - ga.y);
            *(float2*)&of1[jj] = make_float2(acc[fm][fn][2] - gb.x, acc[fm][fn][3] - gb.y);
        }
    }
}

// ======== NN: Y[b,o,col] = sum_k W[o,k] X[b,k,col] (tf32 mma; Wv / Wf) ========
// CTA tile: 256 out-rows (full Cout) x 128 cols.
template<int STATS>
__global__ void __launch_bounds__(256, 1)
k_mma_nn(const float* __restrict__ W, const float* __restrict__ X,
         float* __restrict__ Y, int Cin, int Cout, float* __restrict__ stats)
{
    extern __shared__ float sm[];
    const int tid = threadIdx.x, wid = tid >> 5, lane = tid & 31;
    const int warp_m = wid >> 1, warp_n = wid & 1;
    const int g = lane >> 2, t4 = lane & 3;
    const int b = blockIdx.z;
    const int NCOL = MC * NSAMP;
    const float* Xb = X + (size_t)b * Cin * NCOL;
    const int ncol0 = blockIdx.x * 128;
    const bool al4 = (Cin & 3) == 0;

    float acc[4][8][4];
#pragma unroll
    for (int i = 0; i < 4; i++)
#pragma unroll
        for (int j = 0; j < 8; j++)
#pragma unroll
            for (int p = 0; p < 4; p++) acc[i][j][p] = 0.f;

    float4 pa[8], pb[4];
    const int nch = (Cin + 31) >> 5;

    auto loadA = [&](int k0) {
#pragma unroll
        for (int it = 0; it < 8; it++) {
            int idx = tid + 256*it, row = idx >> 3, f = idx & 7;
            int k = k0 + 4*f;
            const float* wr = &W[(size_t)row*Cin];
            float4 w4;
            if (al4 && k + 3 < Cin) w4 = *(const float4*)&wr[k];
            else {
                w4.x = (k+0 < Cin) ? wr[k+0] : 0.f;
                w4.y = (k+1 < Cin) ? wr[k+1] : 0.f;
                w4.z = (k+2 < Cin) ? wr[k+2] : 0.f;
                w4.w = (k+3 < Cin) ? wr[k+3] : 0.f;
            }
            pa[it] = w4;
        }
    };
    auto loadB = [&](int k0) {
#pragma unroll
        for (int it = 0; it < 4; it++) {
            int kk = k0 + lane;
            int n4 = (tid >> 5) + 8*it;
            float4 x4 = make_float4(0.f, 0.f, 0.f, 0.f);
            if (kk < Cin) x4 = *(const float4*)&Xb[(size_t)kk*NCOL + ncol0 + 4*n4];
            pb[it] = x4;
        }
    };
    auto storeT = [&](int buf) {
        float* As = sm + buf*ATILE;
        float* Bs = sm + 2*ATILE + buf*BTILE;
#pragma unroll
        for (int it = 0; it < 8; it++) {
            int idx = tid + 256*it, row = idx >> 3, f = idx & 7;
            *(float4*)&As[row*TSTR + 4*f] = make_float4(to_tf32(pa[it].x), to_tf32(pa[it].y),
                                                        to_tf32(pa[it].z), to_tf32(pa[it].w));
        }
#pragma unroll
        for (int it = 0; it < 4; it++) {
            int kk = lane;
            int n4 = (tid >> 5) + 8*it;
            Bs[(4*n4 + 0)*TSTR + kk] = to_tf32(pb[it].x);
            Bs[(4*n4 + 1)*TSTR + kk] = to_tf32(pb[it].y);
            Bs[(4*n4 + 2)*TSTR + kk] = to_tf32(pb[it].z);
            Bs[(4*n4 + 3)*TSTR + kk] = to_tf32(pb[it].w);
        }
    };

    loadA(0); loadB(0);
    storeT(0);
    __syncthreads();

    for (int c = 0; c < nch; c++) {
        const int buf = c & 1;
        if (c + 1 < nch) { loadA((c+1)*32); loadB((c+1)*32); }
        mma_tile4(sm + buf*ATILE, sm + 2*ATILE + buf*BTILE, acc, warp_m, warp_n, g, t4);
        if (c + 1 < nch) {
            __syncthreads();
            storeT(buf ^ 1);
            __syncthreads();
        }
    }

#pragma unroll
    for (int fm = 0; fm < 4; fm++) {
        const int r0 = warp_m*64 + fm*16 + g;
        const int r1 = r0 + 8;
        float* y0 = Y + ((size_t)b*Cout + r0)*NCOL + ncol0;
        float* y1 = Y + ((size_t)b*Cout + r1)*NCOL + ncol0;
        float s0 = 0.f, q0 = 0.f, s1 = 0.f, q1 = 0.f;
#pragma unroll
        for (int fn = 0; fn < 8; fn++) {
            const int jj = warp_n*64 + fn*8 + 2*t4;
            float d0 = acc[fm][fn][0], d1 = acc[fm][fn][1];
            float d2 = acc[fm][fn][2], d3 = acc[fm][fn][3];
            *(float2*)&y0[jj] = make_float2(d0, d1);
            *(float2*)&y1[jj] = make_float2(d2, d3);
            if (STATS) {
                s0 += d0 + d1; q0 += d0*d0 + d1*d1;
                s1 += d2 + d3; q1 += d2*d2 + d3*d3;
            }
        }
        if (STATS) {
#pragma unroll
            for (int o = 1; o < 4; o <<= 1) {
                s0 += __shfl_xor_sync(0xffffffffu, s0, o);
                q0 += __shfl_xor_sync(0xffffffffu, q0, o);
                s1 += __shfl_xor_sync(0xffffffffu, s1, o);
                q1 += __shfl_xor_sync(0xffffffffu, q1, o);
            }
            if (t4 == 0) {
                atomicAdd(&stats[r0], s0); atomicAdd(&stats[Cout + r0], q0);
                atomicAdd(&stats[r1], s1); atomicAdd(&stats[Cout + r1], q1);
            }
        }
    }
}

// ---------------- fused q+k projection ----------------
__global__ void k_qk(const float* __restrict__ Wq, const float* __restrict__ Wk,
                     const float* __restrict__ X, float* __restrict__ q,
                     float* __restrict__ k)
{
    const int b = blockIdx.y;
    const int NCOL = MC*NSAMP;
    const float* Xb = X + (size_t)b * 259 * NCOL;
    __shared__ float Ws[16][260];
    for (int i = threadIdx.x; i < 8*259; i += 128) {
        int r = i / 259, c = i % 259;
        Ws[r][c] = Wq[i];
        Ws[r+8][c] = Wk[i];
    }
    __syncthreads();
    int col = blockIdx.x * 128 + threadIdx.x;
    float acc[16];
#pragma unroll
    for (int o = 0; o < 16; o++) acc[o] = 0.f;
    for (int c = 0; c < 259; c++) {
        float xv = Xb[(size_t)c*NCOL + col];
#pragma unroll
        for (int o = 0; o < 16; o++) acc[o] = fmaf(Ws[o][c], xv, acc[o]);
    }
#pragma unroll
    for (int o = 0; o < 8; o++) {
        q[((size_t)b*8 + o)*NCOL + col] = acc[o];
        k[((size_t)b*8 + o)*NCOL + col] = acc[o+8];
    }
}

// ---------------- BN finalize ----------------
__global__ void k_fin(const float* __restrict__ stats, const float* __restrict__ g,
                      const float* __restrict__ be, float* __restrict__ sb,
                      int Cc, float invcnt)
{
    int c = blockIdx.x * 64 + threadIdx.x;
    if (c >= Cc) return;
    float mu  = stats[c] * invcnt;
    float var = stats[Cc + c] * invcnt - mu*mu;
    float s = g[c] * rsqrtf(var + EPSBN);
    sb[c] = s;
    sb[Cc + c] = be[c] - mu * s;
}

// ---------------- ball query ----------------
__global__ void k_bq(const float* __restrict__ src, const float* __restrict__ ctr,
                     int* __restrict__ out, int NSRC)
{
    int gw = (blockIdx.x * blockDim.x + threadIdx.x) >> 5;
    int lane = threadIdx.x & 31;
    __shared__ int lists[8][NSAMP];
    int* list = lists[threadIdx.x >> 5];
    if (gw >= BB*MC) return;
    int b = gw / MC, m = gw % MC;
    float cx = ctr[((size_t)b*MC + m)*3 + 0];
    float cy = ctr[((size_t)b*MC + m)*3 + 1];
    float cz = ctr[((size_t)b*MC + m)*3 + 2];
    int count = 0;
    for (int base = 0; base < NSRC; base += 32) {
        int n = base + lane;
        bool ok = false;
        if (n < NSRC) {
            float dx = src[((size_t)b*NSRC + n)*3 + 0] - cx;
            float dy = src[((size_t)b*NSRC + n)*3 + 1] - cy;
            float dz = src[((size_t)b*NSRC + n)*3 + 2] - cz;
            ok = (dx*dx + dy*dy + dz*dz) < RAD2;
        }
        unsigned mk = __ballot_sync(0xffffffffu, ok);
        if (ok) {
            int pos = count + __popc(mk & ((1u << lane) - 1u));
            if (pos < NSAMP) list[pos] = n;
        }
        count += __popc(mk);
        if (count >= NSAMP) break;
    }
    __syncwarp();
    if (lane < NSAMP) {
        int v;
        if (count == 0) v = 0;
        else v = (lane < count) ? list[lane] : list[0];
        out[((size_t)b*MC + m)*NSAMP + lane] = v;
    }
}

// ---------------- new_features transpose with affine+relu ----------------
__global__ void k_nft(const float* __restrict__ y3, const float* __restrict__ sb3,
                      float* __restrict__ nft)
{
    int b = blockIdx.z;
    int n0 = blockIdx.x * 32, c0 = blockIdx.y * 32;
    __shared__ float t[32][33];
#pragma unroll
    for (int i = 0; i < 4; i++) {
        int c = c0 + threadIdx.y + i*8;
        int n = n0 + threadIdx.x;
        float v = y3[((size_t)b*256 + c)*NPTS + n];
        v = fmaxf(fmaf(v, sb3[c], sb3[256 + c]), 0.f);
        t[threadIdx.y + i*8][threadIdx.x] = v;
    }
    __syncthreads();
#pragma unroll
    for (int i = 0; i < 4; i++) {
        int n = n0 + threadIdx.y + i*8;
        int c = c0 + threadIdx.x;
        nft[((size_t)b*NPTS + n)*256 + c] = t[threadIdx.x][threadIdx.y + i*8];
    }
}

// ---------------- build ip ----------------
__global__ void k_ip(const float* __restrict__ nft, const int* __restrict__ idx1,
                     const int* __restrict__ idx2, const float* __restrict__ xyz,
                     const float* __restrict__ ctr, float* __restrict__ ip)
{
    int bz = blockIdx.x;
    int cblk = bz & 31;
    int slot = (bz >> 5) & 15;
    int b    = bz >> 9;
    __shared__ float s[256][33];
    int warp = threadIdx.x >> 5, lane = threadIdx.x & 31;
#pragma unroll
    for (int w = 0; w < 4; w++) {
        int center = cblk*32 + warp*4 + w;
        int id = idx1[((size_t)b*MC + center)*NSAMP + slot];
        const float* srcp = nft + ((size_t)b*NPTS + id)*256;
#pragma unroll
        for (int t = 0; t < 8; t++) s[lane + t*32][warp*4 + w] = srcp[lane + t*32];
    }
    __syncthreads();
    int center = threadIdx.x & 31, chb = threadIdx.x >> 5;
#pragma unroll
    for (int t = 0; t < 32; t++) {
        int ch = chb + t*8;
        ip[(((size_t)b*259 + ch)*NSAMP + slot)*MC + cblk*32 + center] = s[ch][center];
    }
    if (threadIdx.x < 96) {
        int d = threadIdx.x / 32;
        int cc = threadIdx.x & 31;
        int ctr_i = cblk*32 + cc;
        int i1 = idx1[((size_t)b*MC + ctr_i)*NSAMP + slot];
        int i2 = idx2[((size_t)b*MC + ctr_i)*NSAMP + slot];
        float r = ctr[((size_t)b*MC + i2)*3 + d] - xyz[((size_t)b*NPTS + i1)*3 + d];
        ip[(((size_t)b*259 + 256 + d)*NSAMP + slot)*MC + ctr_i] = r;
    }
}

// ---------------- attention: warp-per-column softmax ----------------
__global__ void __launch_bounds__(256)
k_att(const float* __restrict__ q, const float* __restrict__ k,
      float* __restrict__ P)
{
    int bx = blockIdx.x;
    int jblk = bx & 127;          // MC/8
    int slot = (bx >> 7) & 15;
    int b = bx >> 11;
    int wid = threadIdx.x >> 5, lane = threadIdx.x & 31;
    int j = jblk*8 + wid;
    const float* qb = q + ((size_t)b*8*NSAMP + slot)*MC;
    const float* kb = k + ((size_t)b*8*NSAMP + slot)*MC;
    float tq = (lane < 8) ? qb[(size_t)lane*NSAMP*MC + j] : 0.f;
    float qv[8];
#pragma unroll
    for (int c = 0; c < 8; c++) qv[c] = __shfl_sync(0xffffffffu, tq, c);

    float s[32];
#pragma unroll
    for (int it = 0; it < 32; it++) {
        int n = it*32 + lane;
        float a = 0.f;
#pragma unroll
        for (int c = 0; c < 8; c++) a = fmaf(kb[(size_t)c*NSAMP*MC + n], qv[c], a);
        s[it] = a;
    }
    float mx = s[0];
#pragma unroll
    for (int it = 1; it < 32; it++) mx = fmaxf(mx, s[it]);
#pragma unroll
    for (int o = 16; o > 0; o >>= 1) mx = fmaxf(mx, __shfl_xor_sync(0xffffffffu, mx, o));
    float sum = 0.f;
#pragma unroll
    for (int it = 0; it < 32; it++) { s[it] = __expf(s[it] - mx); sum += s[it]; }
#pragma unroll
    for (int o = 16; o > 0; o >>= 1) sum += __shfl_xor_sync(0xffffffffu, sum, o);
    float inv = 1.f / sum;
    float* Pr = P + (((size_t)(b*NSAMP + slot))*MC + j)*MC;
#pragma unroll
    for (int it = 0; it < 32; it++) Pr[it*32 + lane] = s[it] * inv;
}

// ---------------- relu(affine(yf)) + gf residual, max-pool over slot ----------------
__global__ void k_pool(const float* __restrict__ yf, const float* __restrict__ sbf,
                       const float* __restrict__ ip, float* __restrict__ pool)
{
    int i = blockIdx.x * 256 + threadIdx.x;
    if (i >= BB*256*MC) return;
    int center = i & (MC-1);
    int c = (i >> 10) & 255;
    int b = i >> 18;
    float s = sbf[c], bi = sbf[256 + c];
    float mx = -1e30f;
#pragma unroll
    for (int slot = 0; slot < NSAMP; slot++) {
        float v = fmaxf(fmaf(yf[(((size_t)b*256 + c)*NSAMP + slot)*MC + center], s, bi), 0.f);
        v += ip[(((size_t)b*259 + c)*NSAMP + slot)*MC + center];
        mx = fmaxf(mx, v);
    }
    pool[((size_t)b*256 + c)*MC + center] = mx;
}

// ---------------- final ----------------
__global__ void k_final(const float* __restrict__ yo, const float* __restrict__ sbo,
                        const float* __restrict__ ctr, float* __restrict__ out, int has_ctr)
{
    int off0 = has_ctr ? BB*MC*3 : 0;
    int total = off0 + BB*512*MC;
    int i = blockIdx.x * 256 + threadIdx.x;
    if (i >= total) return;
    if (i < off0) { out[i] = ctr[i]; return; }
    int j = i - off0;
    int ch = (j >> 10) & 511;
    out[i] = fmaxf(fmaf(yo[j], sbo[ch], sbo[512 + ch]), 0.f);
}

// ---------------- host launch ----------------
extern "C" void kernel_launch(void* const* d_in, const int* in_sizes, int n_in,
                              void* d_out, int out_size)
{
    const float* xyz   = (const float*)d_in[0];
    const float* feats = (const float*)d_in[1];
    const float* ctr   = (const float*)d_in[2];
    const float* W1 = (const float*)d_in[3];
    const float* g1 = (const float*)d_in[4];
    const float* b1 = (const float*)d_in[5];
    const float* W2 = (const float*)d_in[6];
    const float* g2 = (const float*)d_in[7];
    const float* b2 = (const float*)d_in[8];
    const float* W3 = (const float*)d_in[9];
    const float* g3 = (const float*)d_in[10];
    const float* b3 = (const float*)d_in[11];
    const float* Wq = (const float*)d_in[12];
    const float* Wk = (const float*)d_in[13];
    const float* Wv = (const float*)d_in[14];
    const float* Wf = (const float*)d_in[15];
    const float* gp = (const float*)d_in[16];
    const float* bp = (const float*)d_in[17];
    const float* Wo = (const float*)d_in[18];
    const float* go = (const float*)d_in[19];
    const float* bo = (const float*)d_in[20];
    float* outp = (float*)d_out;

    float *featin, *y1, *y2, *y3, *nft, *ip, *qb, *kb, *vb, *Pb, *offb, *yf, *pool, *yo;
    int *idx1, *idx2;
    float *st1, *st2, *st3, *stf, *sto, *sb1, *sb2, *sb3, *sbf, *sbo;
    cudaGetSymbolAddress((void**)&featin, g_featin);
    cudaGetSymbolAddress((void**)&y1, g_y1);
    cudaGetSymbolAddress((void**)&y2, g_y2);
    cudaGetSymbolAddress((void**)&y3, g_y3);
    cudaGetSymbolAddress((void**)&nft, g_nft);
    cudaGetSymbolAddress((void**)&idx1, g_idx1);
    cudaGetSymbolAddress((void**)&idx2, g_idx2);
    cudaGetSymbolAddress((void**)&ip, g_ip);
    cudaGetSymbolAddress((void**)&qb, g_q);
    cudaGetSymbolAddress((void**)&kb, g_k);
    cudaGetSymbolAddress((void**)&vb, g_v);
    cudaGetSymbolAddress((void**)&Pb, g_P);
    cudaGetSymbolAddress((void**)&offb, g_off);
    cudaGetSymbolAddress((void**)&yf, g_yf);
    cudaGetSymbolAddress((void**)&pool, g_pool);
    cudaGetSymbolAddress((void**)&yo, g_yo);
    cudaGetSymbolAddress((void**)&st1, g_st1);
    cudaGetSymbolAddress((void**)&st2, g_st2);
    cudaGetSymbolAddress((void**)&st3, g_st3);
    cudaGetSymbolAddress((void**)&stf, g_stf);
    cudaGetSymbolAddress((void**)&sto, g_sto);
    cudaGetSymbolAddress((void**)&sb1, g_sb1);
    cudaGetSymbolAddress((void**)&sb2, g_sb2);
    cudaGetSymbolAddress((void**)&sb3, g_sb3);
    cudaGetSymbolAddress((void**)&sbf, g_sbf);
    cudaGetSymbolAddress((void**)&sbo, g_sbo);

    cudaFuncSetAttribute(k_mma_nt, cudaFuncAttributeMaxDynamicSharedMemorySize, MMA_SMEM_BYTES);
    cudaFuncSetAttribute(k_mma_nn<0>, cudaFuncAttributeMaxDynamicSharedMemorySize, MMA_SMEM_BYTES);
    cudaFuncSetAttribute(k_mma_nn<1>, cudaFuncAttributeMaxDynamicSharedMemorySize, MMA_SMEM_BYTES);

    cudaMemsetAsync(st1, 0, sizeof(float)*2*64,  0);
    cudaMemsetAsync(st2, 0, sizeof(float)*2*128, 0);
    cudaMemsetAsync(st3, 0, sizeof(float)*2*256, 0);
    cudaMemsetAsync(stf, 0, sizeof(float)*2*256, 0);
    cudaMemsetAsync(sto, 0, sizeof(float)*2*512, 0);

    k_featin<<<(BB*67*NPTS + 255)/256, 256>>>(xyz, feats, featin);

    // MLP (FFMA2, fp32 — trunk precision)
    k_gemm2<0,1><<<dim3(NPTS/128, 1, BB), 256>>>(W1, featin, y1, 67, 64, NPTS, nullptr, st1);
    k_fin<<<1, 64>>>(st1, g1, b1, sb1, 64, 1.f/(BB*NPTS));
    k_gemm2<1,1><<<dim3(NPTS/128, 2, BB), 256>>>(W2, y1, y2, 64, 128, NPTS, sb1, st2);
    k_fin<<<2, 64>>>(st2, g2, b2, sb2, 128, 1.f/(BB*NPTS));
    k_gemm2<1,1><<<dim3(NPTS/128, 4, BB), 256>>>(W3, y2, y3, 128, 256, NPTS, sb2, st3);
    k_fin<<<4, 64>>>(st3, g3, b3, sb3, 256, 1.f/(BB*NPTS));

    k_nft<<<dim3(NPTS/32, 8, BB), dim3(32, 8)>>>(y3, sb3, nft);

    k_bq<<<(BB*MC*32 + 255)/256, 256>>>(xyz, ctr, idx1, NPTS);
    k_bq<<<(BB*MC*32 + 255)/256, 256>>>(ctr, ctr, idx2, MC);

    k_ip<<<BB*16*32, 256>>>(nft, idx1, idx2, xyz, ctr, ip);

    // q, k (fused FFMA), v (tf32 mma, 256-row tile)
    k_qk<<<dim3(MC*NSAMP/128, BB), 128>>>(Wq, Wk, ip, qb, kb);
    k_mma_nn<0><<<dim3(128, 1, BB), 256, MMA_SMEM_BYTES>>>(Wv, ip, vb, 259, 256, nullptr);

    // attention: warp-per-j softmax, then V P^T (tf32 mma, 256-row tile)
    k_att<<<BB*NSAMP*(MC/8), 256>>>(qb, kb, Pb);
    k_mma_nt<<<dim3(8, 1, BB*NSAMP), 256, MMA_SMEM_BYTES>>>(vb, Pb, ip, offb);

    // Wf (tf32 mma + BN stats, 256-row tile), pool
    k_mma_nn<1><<<dim3(128, 1, BB), 256, MMA_SMEM_BYTES>>>(Wf, offb, yf, 256, 256, stf);
    k_fin<<<4, 64>>>(stf, gp, bp, sbf, 256, 1.f/(BB*MC*NSAMP));
    k_pool<<<(BB*256*MC + 255)/256, 256>>>(yf, sbf, ip, pool);

    // output conv (FFMA2, fp32)
    k_gemm2<0,1><<<dim3(MC/128, 8, BB), 256>>>(Wo, pool, yo, 256, 512, MC, nullptr, sto);
    k_fin<<<8, 64>>>(sto, go, bo, sbo, 512, 1.f/(BB*MC));

    int has_ctr = (out_size == BB*MC*3 + BB*512*MC) ? 1 : 0;
    int total = (has_ctr ? BB*MC*3 : 0) + BB*512*MC;
    k_final<<<(total + 255)/256, 256>>>(yo, sbo, ctr, outp, has_ctr);
}